// round 13
// baseline (speedup 1.0000x reference)
#include <cuda_runtime.h>
#include <cuda_fp16.h>
#include <cstdint>
#include <math.h>

// ---------------- problem constants ----------------
#define Bb   8
#define Tt   2048
#define Cc   768
#define WDd  512
#define TDd  384
#define CDd  3072
#define H1h  768
#define MTOK (Bb * Tt)          // 16384

// ---------------- fp32 scratch ----------------
__device__ float g_x2 [MTOK * Cc];
__device__ float g_h1 [MTOK * TDd];
__device__ float g_mix[Bb * TDd * Cc];
__device__ float g_s12[Bb * H1h];
__device__ float g_ss [Bb * (CDd/2)];
__device__ float g_zero[CDd];
__device__ float g_bil[6144];

// ---------------- fp16 split operand buffers ----------------
__device__ __half g_xh [MTOK*Cc],        g_xl [MTOK*Cc];
__device__ __half g_a12h[MTOK*H1h],      g_a12l[MTOK*H1h];
__device__ __half g_ash[MTOK*(CDd/2)],   g_asl[MTOK*(CDd/2)];
__device__ __half g_h2h[MTOK*TDd],       g_h2l[MTOK*TDd];
__device__ __half g_h1th[Bb*TDd*Tt],     g_h1tl[Bb*TDd*Tt];
__device__ __half g_xTh[Bb*Cc*Tt],       g_xTl[Bb*Cc*Tt];
__device__ __half g_mTh[Bb*Cc*TDd],      g_mTl[Bb*Cc*TDd];
__device__ __half g_x3h[MTOK*Cc],        g_x3l[MTOK*Cc];

// dedicated transposed-weight slices (hi/lo)
#define W0_OFF 0
#define W1_OFF (W0_OFF + 2*H1h*Cc)
#define W2_OFF (W1_OFF + TDd*TDd)
#define W3_OFF (W2_OFF + TDd*TDd)
#define W4_OFF (W3_OFF + CDd*Cc)
#define W5_OFF (W4_OFF + (CDd/2)*Cc)
#define W6_OFF (W5_OFF + Cc*Cc)
#define W_TOT  (W6_OFF + (Cc/2)*Cc)
__device__ __half g_wTh[W_TOT], g_wTl[W_TOT];

// ---------------- helpers ----------------
__device__ __forceinline__ uint32_t smem_u32(const void* p) {
    uint32_t a;
    asm("{ .reg .u64 t; cvta.to.shared.u64 t, %1; cvt.u32.u64 %0, t; }" : "=r"(a) : "l"(p));
    return a;
}
__device__ __forceinline__ void cpa16(uint32_t s, const void* g) {
    asm volatile("cp.async.cg.shared.global [%0], [%1], 16;" :: "r"(s), "l"(g));
}
__device__ __forceinline__ void ldsm4(uint32_t& r0, uint32_t& r1, uint32_t& r2, uint32_t& r3,
                                      uint32_t a) {
    asm volatile("ldmatrix.sync.aligned.m8n8.x4.shared.b16 {%0,%1,%2,%3}, [%4];"
                 : "=r"(r0), "=r"(r1), "=r"(r2), "=r"(r3) : "r"(a));
}
// fp16 inputs, f32 accumulate (main term)
__device__ __forceinline__ void mma_f32a(float* c, const uint32_t* a,
                                         uint32_t b0, uint32_t b1) {
    asm volatile(
        "mma.sync.aligned.m16n8k16.row.col.f32.f16.f16.f32 "
        "{%0,%1,%2,%3}, {%4,%5,%6,%7}, {%8,%9}, {%0,%1,%2,%3};"
        : "+f"(c[0]), "+f"(c[1]), "+f"(c[2]), "+f"(c[3])
        : "r"(a[0]), "r"(a[1]), "r"(a[2]), "r"(a[3]), "r"(b0), "r"(b1));
}
// fp16 inputs, f16 accumulate (cross terms; 2 packed regs)
__device__ __forceinline__ void mma_f16a(uint32_t* c, const uint32_t* a,
                                         uint32_t b0, uint32_t b1) {
    asm volatile(
        "mma.sync.aligned.m16n8k16.row.col.f16.f16.f16.f16 "
        "{%0,%1}, {%2,%3,%4,%5}, {%6,%7}, {%0,%1};"
        : "+r"(c[0]), "+r"(c[1])
        : "r"(a[0]), "r"(a[1]), "r"(a[2]), "r"(a[3]), "r"(b0), "r"(b1));
}
__device__ __forceinline__ void split_one(float v, __half& h, __half& l) {
    h = __float2half_rn(v);
    l = __float2half_rn(v - __half2float(h));
}

// ================= split-fp16 GEMM: BK=32, 2-stage cp.async ======================
// hi term -> f32-acc HMMA; both cross terms -> shared f16-acc HMMA.
#define LDBB 80
#define TILE_B (128 * LDBB)
#define GSMEM_SZ (8 * TILE_B)

template <int ACT>
__global__ void __launch_bounds__(256, 2) gemm_sp(
    const __half* __restrict__ Ah_, const __half* __restrict__ Al_,
    const __half* __restrict__ Bh_, const __half* __restrict__ Bl_,
    float* __restrict__ Cf, __half* __restrict__ Ch, __half* __restrict__ Cl,
    const float* __restrict__ bias, const float* __restrict__ resF,
    const __half* __restrict__ resH, const __half* __restrict__ resL,
    const float* __restrict__ scale, int sN,
    int M, int N, int K, int lda,
    long long sA, long long sB, long long sC, long long sR)
{
    extern __shared__ char smem[];
    const uint32_t sbase = smem_u32(smem);
    const int tid = threadIdx.x, wid = tid >> 5, lane = tid & 31;
    const int g = lane >> 2, tg = lane & 3;
    const int wm = (wid >> 1) * 32;
    const int wn = (wid & 1) * 64;

    const int bz = blockIdx.z;
    const long long ldaB = (long long)lda * 2;
    const long long ldbB = (long long)K * 2;

    const int row0 = blockIdx.y * 128;
    const int col0 = blockIdx.x * 128;

    const char* Agh = (const char*)(Ah_ + bz * sA) + (long long)row0 * ldaB;
    const char* Agl = (const char*)(Al_ + bz * sA) + (long long)row0 * ldaB;
    const char* Bgh = (const char*)(Bh_ + bz * sB) + (long long)col0 * ldbB;
    const char* Bgl = (const char*)(Bl_ + bz * sB) + (long long)col0 * ldbB;
    if (Cf) Cf += bz * sC;
    if (Ch) { Ch += bz * sC; Cl += bz * sC; }
    if (resF) resF += bz * sR;
    if (resH) { resH += bz * sR; resL += bz * sR; }

    const int nIter = K >> 5;
    const int rr = tid >> 2;
    const int cbo = (tid & 3) * 16;

    auto issue = [&](int i) {
        const uint32_t sb0 = sbase + (uint32_t)(i & 1) * 4 * TILE_B;
        const long long ko = (long long)i * 64;
#pragma unroll
        for (int t = 0; t < 2; t++) {
            const int r = rr + t * 64;
            const uint32_t so = (uint32_t)r * LDBB + cbo;
            cpa16(sb0 + so,              Agh + (long long)r * ldaB + ko + cbo);
            cpa16(sb0 + TILE_B + so,     Agl + (long long)r * ldaB + ko + cbo);
            cpa16(sb0 + 2 * TILE_B + so, Bgh + (long long)r * ldbB + ko + cbo);
            cpa16(sb0 + 3 * TILE_B + so, Bgl + (long long)r * ldbB + ko + cbo);
        }
    };

    issue(0); asm volatile("cp.async.commit_group;");
    issue(1); asm volatile("cp.async.commit_group;");

    const uint32_t aOff0 = (uint32_t)(wm + (lane & 7) + ((lane >> 3) & 1) * 8) * LDBB
                         + (uint32_t)(lane >> 4) * 16;
    const uint32_t aOff1 = aOff0 + 16 * LDBB;
    const uint32_t bOff0 = (uint32_t)(wn + (lane & 7) + (lane >> 4) * 8) * LDBB
                         + (uint32_t)((lane >> 3) & 1) * 16;

    float accH[2][8][4];
    uint32_t accL[2][8][2];
#pragma unroll
    for (int mt = 0; mt < 2; mt++)
#pragma unroll
        for (int nt = 0; nt < 8; nt++) {
#pragma unroll
            for (int q = 0; q < 4; q++) accH[mt][nt][q] = 0.f;
            accL[mt][nt][0] = 0u; accL[mt][nt][1] = 0u;
        }

    for (int i = 0; i < nIter; i++) {
        asm volatile("cp.async.wait_group 1;");
        __syncthreads();
        const uint32_t st = sbase + (uint32_t)(i & 1) * 4 * TILE_B;
#pragma unroll
        for (int kk = 0; kk < 2; kk++) {
            const uint32_t kb = kk * 32;
            // ---- A-hi phase: ah*bh (f32) and ah*bl (f16) ----
            {
                uint32_t ah[2][4];
                ldsm4(ah[0][0], ah[0][1], ah[0][2], ah[0][3], st + aOff0 + kb);
                ldsm4(ah[1][0], ah[1][1], ah[1][2], ah[1][3], st + aOff1 + kb);
#pragma unroll
                for (int ntp = 0; ntp < 4; ntp++) {
                    const int n0 = 2 * ntp, n1 = 2 * ntp + 1;
                    const uint32_t bo = bOff0 + (uint32_t)ntp * 16 * LDBB + kb;
                    uint32_t bh0, bh1, bh2, bh3;
                    ldsm4(bh0, bh1, bh2, bh3, st + 2 * TILE_B + bo);
                    mma_f32a(accH[0][n0], ah[0], bh0, bh1);
                    mma_f32a(accH[1][n0], ah[1], bh0, bh1);
                    mma_f32a(accH[0][n1], ah[0], bh2, bh3);
                    mma_f32a(accH[1][n1], ah[1], bh2, bh3);
                    uint32_t bl0, bl1, bl2, bl3;
                    ldsm4(bl0, bl1, bl2, bl3, st + 3 * TILE_B + bo);
                    mma_f16a(accL[0][n0], ah[0], bl0, bl1);
                    mma_f16a(accL[1][n0], ah[1], bl0, bl1);
                    mma_f16a(accL[0][n1], ah[0], bl2, bl3);
                    mma_f16a(accL[1][n1], ah[1], bl2, bl3);
                }
            }
            // ---- A-lo phase: al*bh (f16) ----
            {
                uint32_t al[2][4];
                ldsm4(al[0][0], al[0][1], al[0][2], al[0][3], st + TILE_B + aOff0 + kb);
                ldsm4(al[1][0], al[1][1], al[1][2], al[1][3], st + TILE_B + aOff1 + kb);
#pragma unroll
                for (int ntp = 0; ntp < 4; ntp++) {
                    const int n0 = 2 * ntp, n1 = 2 * ntp + 1;
                    const uint32_t bo = bOff0 + (uint32_t)ntp * 16 * LDBB + kb;
                    uint32_t bh0, bh1, bh2, bh3;
                    ldsm4(bh0, bh1, bh2, bh3, st + 2 * TILE_B + bo);
                    mma_f16a(accL[0][n0], al[0], bh0, bh1);
                    mma_f16a(accL[1][n0], al[1], bh0, bh1);
                    mma_f16a(accL[0][n1], al[0], bh2, bh3);
                    mma_f16a(accL[1][n1], al[1], bh2, bh3);
                }
            }
        }
        __syncthreads();
        if (i + 2 < nIter) issue(i + 2);
        asm volatile("cp.async.commit_group;");
    }
    asm volatile("cp.async.wait_all;");

    // ---- epilogue ----
    const int Nout = (ACT == 2) ? (N >> 1) : N;
#pragma unroll
    for (int mt = 0; mt < 2; mt++) {
        const int r = row0 + wm + mt * 16 + g;
#pragma unroll
        for (int nt = 0; nt < 8; nt++) {
            const int c = col0 + wn + nt * 8 + tg * 2;
            const float bx = __ldg(&bias[c]), by = __ldg(&bias[c + 1]);
            const __half2 lo0 = *(__half2*)&accL[mt][nt][0];   // row r   : c, c+1
            const __half2 lo1 = *(__half2*)&accL[mt][nt][1];   // row r+8 : c, c+1
            float v0 = accH[mt][nt][0] + __half2float(lo0.x) + bx;
            float v1 = accH[mt][nt][1] + __half2float(lo0.y) + by;
            float v2 = accH[mt][nt][2] + __half2float(lo1.x) + bx;
            float v3 = accH[mt][nt][3] + __half2float(lo1.y) + by;
            if (ACT == 2) {
                const int c2 = c >> 1;
                float o0 = v0 / (1.0f + __expf(-v1));
                float o1 = v2 / (1.0f + __expf(-v3));
                if (scale) {
                    o0 *= __ldg(&scale[(r / Tt) * sN + c2]);
                    o1 *= __ldg(&scale[((r + 8) / Tt) * sN + c2]);
                }
                __half h0, l0, h1, l1;
                split_one(o0, h0, l0); split_one(o1, h1, l1);
                Ch[(long long)r * Nout + c2] = h0;
                Cl[(long long)r * Nout + c2] = l0;
                Ch[(long long)(r + 8) * Nout + c2] = h1;
                Cl[(long long)(r + 8) * Nout + c2] = l1;
            } else {
                if (resF) {
                    const float2 r0 = *(const float2*)(resF + (long long)r * N + c);
                    const float2 r1 = *(const float2*)(resF + (long long)(r + 8) * N + c);
                    v0 += r0.x; v1 += r0.y; v2 += r1.x; v3 += r1.y;
                }
                if (resH) {
                    const __half2 h0 = *(const __half2*)(resH + (long long)r * N + c);
                    const __half2 l0 = *(const __half2*)(resL + (long long)r * N + c);
                    const __half2 h1 = *(const __half2*)(resH + (long long)(r + 8) * N + c);
                    const __half2 l1 = *(const __half2*)(resL + (long long)(r + 8) * N + c);
                    v0 += __half2float(h0.x) + __half2float(l0.x);
                    v1 += __half2float(h0.y) + __half2float(l0.y);
                    v2 += __half2float(h1.x) + __half2float(l1.x);
                    v3 += __half2float(h1.y) + __half2float(l1.y);
                }
                if (ACT == 1) {
                    v0 = 0.5f * v0 * (1.0f + erff(v0 * 0.70710678118654752f));
                    v1 = 0.5f * v1 * (1.0f + erff(v1 * 0.70710678118654752f));
                    v2 = 0.5f * v2 * (1.0f + erff(v2 * 0.70710678118654752f));
                    v3 = 0.5f * v3 * (1.0f + erff(v3 * 0.70710678118654752f));
                }
                if (Cf) {
                    *(float2*)(Cf + (long long)r * N + c)       = make_float2(v0, v1);
                    *(float2*)(Cf + (long long)(r + 8) * N + c) = make_float2(v2, v3);
                }
                if (Ch) {
                    __half2 h01, l01, h23, l23;
                    split_one(v0, h01.x, l01.x); split_one(v1, h01.y, l01.y);
                    split_one(v2, h23.x, l23.x); split_one(v3, h23.y, l23.y);
                    *(__half2*)(Ch + (long long)r * N + c)       = h01;
                    *(__half2*)(Cl + (long long)r * N + c)       = l01;
                    *(__half2*)(Ch + (long long)(r + 8) * N + c) = h23;
                    *(__half2*)(Cl + (long long)(r + 8) * N + c) = l23;
                }
            }
        }
    }
}

// ================= transpose + split (fp32 src) =================
__global__ void transpose_split(const float* __restrict__ in,
                                __half* __restrict__ oh, __half* __restrict__ ol,
                                int R, int Cn, long long sIn, long long sOut)
{
    __shared__ float t[32][33];
    const int bz = blockIdx.z;
    in += bz * sIn; oh += bz * sOut; ol += bz * sOut;
    const int c0 = blockIdx.x * 32, r0 = blockIdx.y * 32;
    const int x = threadIdx.x, y = threadIdx.y;
#pragma unroll
    for (int dy = 0; dy < 32; dy += 8)
        t[y + dy][x] = in[(long long)(r0 + y + dy) * Cn + c0 + x];
    __syncthreads();
#pragma unroll
    for (int dy = 0; dy < 32; dy += 8) {
        __half h, l;
        split_one(t[x][y + dy], h, l);
        const long long o = (long long)(c0 + y + dy) * R + r0 + x;
        oh[o] = h; ol[o] = l;
    }
}

// transpose of an already-split pair
__global__ void transpose_hf2(const __half* __restrict__ ih, const __half* __restrict__ il,
                              __half* __restrict__ oh, __half* __restrict__ ol,
                              int R, int Cn, long long sIn, long long sOut)
{
    __shared__ __half th[32][34];
    __shared__ __half tl[32][34];
    const int bz = blockIdx.z;
    ih += bz * sIn; il += bz * sIn; oh += bz * sOut; ol += bz * sOut;
    const int c0 = blockIdx.x * 32, r0 = blockIdx.y * 32;
    const int x = threadIdx.x, y = threadIdx.y;
#pragma unroll
    for (int dy = 0; dy < 32; dy += 8) {
        const long long o = (long long)(r0 + y + dy) * Cn + c0 + x;
        th[y + dy][x] = ih[o];
        tl[y + dy][x] = il[o];
    }
    __syncthreads();
#pragma unroll
    for (int dy = 0; dy < 32; dy += 8) {
        const long long o = (long long)(c0 + y + dy) * R + r0 + x;
        oh[o] = th[x][y + dy];
        ol[o] = tl[x][y + dy];
    }
}

// transpose + split + interleave dest rows for GLU-fused GEMM
__global__ void transpose_split_il(const float* __restrict__ in,
                                   __half* __restrict__ oh, __half* __restrict__ ol,
                                   int R, int Cn, int Hhalf)
{
    __shared__ float t[32][33];
    const int c0 = blockIdx.x * 32, r0 = blockIdx.y * 32;
    const int x = threadIdx.x, y = threadIdx.y;
#pragma unroll
    for (int dy = 0; dy < 32; dy += 8)
        t[y + dy][x] = in[(long long)(r0 + y + dy) * Cn + c0 + x];
    __syncthreads();
#pragma unroll
    for (int dy = 0; dy < 32; dy += 8) {
        const int c = c0 + y + dy;
        const int dr = (c < Hhalf) ? 2 * c : 2 * (c - Hhalf) + 1;
        __half h, l;
        split_one(t[x][y + dy], h, l);
        const long long o = (long long)dr * R + r0 + x;
        oh[o] = h; ol[o] = l;
    }
}

// z-batched variant for g1|g2
__global__ void transpose_split_il2(const float* __restrict__ g1W,
                                    const float* __restrict__ g2W,
                                    __half* __restrict__ oh, __half* __restrict__ ol)
{
    __shared__ float t[32][33];
    const float* in = blockIdx.z ? g2W : g1W;
    const long long dofs = blockIdx.z ? (long long)H1h * Cc : 0;
    const int c0 = blockIdx.x * 32, r0 = blockIdx.y * 32;
    const int x = threadIdx.x, y = threadIdx.y;
#pragma unroll
    for (int dy = 0; dy < 32; dy += 8)
        t[y + dy][x] = in[(long long)(r0 + y + dy) * H1h + c0 + x];
    __syncthreads();
#pragma unroll
    for (int dy = 0; dy < 32; dy += 8) {
        const int c = c0 + y + dy;
        const int dr = (c < H1h/2) ? 2 * c : 2 * (c - H1h/2) + 1;
        __half h, l;
        split_one(t[x][y + dy], h, l);
        const long long o = dofs + (long long)dr * Cc + r0 + x;
        oh[o] = h; ol[o] = l;
    }
}

// ================= LayerNorm + split (C=768) =================
__global__ __launch_bounds__(256) void ln_split(const float* __restrict__ x,
                                                const float* __restrict__ g,
                                                const float* __restrict__ b,
                                                __half* __restrict__ oh,
                                                __half* __restrict__ ol)
{
    const int row = blockIdx.x;
    const float* xr = x + (long long)row * Cc;
    const int tid = threadIdx.x;

    float v0 = xr[tid], v1 = xr[tid + 256], v2 = xr[tid + 512];
    float s = v0 + v1 + v2;
    float q = v0 * v0 + v1 * v1 + v2 * v2;
    for (int off = 16; off > 0; off >>= 1) {
        s += __shfl_down_sync(0xffffffff, s, off);
        q += __shfl_down_sync(0xffffffff, q, off);
    }
    __shared__ float ssm[8], sqm[8];
    const int wid = tid >> 5, lid = tid & 31;
    if (lid == 0) { ssm[wid] = s; sqm[wid] = q; }
    __syncthreads();
    if (tid < 8) { s = ssm[tid]; q = sqm[tid]; }
    if (wid == 0) {
        for (int off = 4; off > 0; off >>= 1) {
            s += __shfl_down_sync(0x000000ff, s, off);
            q += __shfl_down_sync(0x000000ff, q, off);
        }
        if (tid == 0) { ssm[0] = s; sqm[0] = q; }
    }
    __syncthreads();
    const float mu  = ssm[0] * (1.0f / Cc);
    const float var = sqm[0] * (1.0f / Cc) - mu * mu;
    const float rs  = rsqrtf(var + 1e-6f);

#pragma unroll
    for (int t = 0; t < 3; t++) {
        const int j = tid + t * 256;
        const float vv = t == 0 ? v0 : (t == 1 ? v1 : v2);
        const float v = (vv - mu) * rs * g[j] + b[j];
        const long long o = (long long)row * Cc + j;
        __half h, l;
        split_one(v, h, l);
        oh[o] = h; ol[o] = l;
    }
}

// ================= all small prep in ONE launch =================
__global__ __launch_bounds__(256) void prep_small(
    const float* __restrict__ w,
    const float* __restrict__ s1_W, const float* __restrict__ s1_b,
    const float* __restrict__ s2_W, const float* __restrict__ s2_b,
    const float* __restrict__ ss_W, const float* __restrict__ ss_b,
    const float* __restrict__ g1_b, const float* __restrict__ g2_b,
    const float* __restrict__ gs_b, const float* __restrict__ r1_b,
    float* __restrict__ s12, float* __restrict__ ssv, float* __restrict__ bil)
{
    const int blk = blockIdx.x;
    if (blk < 576) {
        const float* W; const float* bias; float* out; int N, ldout, b, n0;
        const float* wr;
        if (blk < 96)       { const int i = blk;       b = i / 12; n0 = (i % 12) * 32; W = s1_W; bias = s1_b; out = s12;           N = TDd;   ldout = H1h;   wr = w + (long long)b * 2 * WDd; }
        else if (blk < 192) { const int i = blk - 96;  b = i / 12; n0 = (i % 12) * 32; W = s2_W; bias = s2_b; out = s12 + TDd;     N = TDd;   ldout = H1h;   wr = w + (long long)b * 2 * WDd; }
        else                { const int i = blk - 192; b = i / 48; n0 = (i % 48) * 32; W = ss_W; bias = ss_b; out = ssv;           N = CDd/2; ldout = CDd/2; wr = w + (long long)b * 2 * WDd + WDd; }
        __shared__ float ws[WDd];
        __shared__ float red[8][32];
        for (int k = threadIdx.x; k < WDd; k += 256) ws[k] = wr[k];
        __syncthreads();
        const int lane = threadIdx.x & 31, sct = threadIdx.x >> 5;
        const int n = n0 + lane;
        float acc = 0.f;
#pragma unroll 4
        for (int k = sct * 64; k < sct * 64 + 64; k++)
            acc = fmaf(ws[k], W[(long long)k * N + n], acc);
        red[sct][lane] = acc;
        __syncthreads();
        if (sct == 0) {
            float a = red[0][lane];
#pragma unroll
            for (int j = 1; j < 8; j++) a += red[j][lane];
            out[(long long)b * ldout + n] = a + bias[n];
        }
    } else {
        const int i = (blk - 576) * 256 + threadIdx.x;
        if (i < 768)       bil[i] = g1_b[(i >> 1) + (i & 1) * (H1h/2)];
        else if (i < 1536) { const int j = i - 768;  bil[i] = g2_b[(j >> 1) + (j & 1) * (H1h/2)]; }
        else if (i < 4608) { const int j = i - 1536; bil[i] = gs_b[(j >> 1) + (j & 1) * (CDd/2)]; }
        else if (i < 5376) { const int j = i - 4608; bil[i] = r1_b[(j >> 1) + (j & 1) * (Cc/2)]; }
    }
}

// ================= streams/events (created once at program load) ================
struct StreamPack {
    cudaStream_t s1, s2;
    cudaEvent_t eF, eLN, ePrep, eW0, eWall, eA12, eXT, eH2;
    StreamPack() {
        cudaStreamCreateWithFlags(&s1, cudaStreamNonBlocking);
        cudaStreamCreateWithFlags(&s2, cudaStreamNonBlocking);
        cudaEventCreateWithFlags(&eF,    cudaEventDisableTiming);
        cudaEventCreateWithFlags(&eLN,   cudaEventDisableTiming);
        cudaEventCreateWithFlags(&ePrep, cudaEventDisableTiming);
        cudaEventCreateWithFlags(&eW0,   cudaEventDisableTiming);
        cudaEventCreateWithFlags(&eWall, cudaEventDisableTiming);
        cudaEventCreateWithFlags(&eA12,  cudaEventDisableTiming);
        cudaEventCreateWithFlags(&eXT,   cudaEventDisableTiming);
        cudaEventCreateWithFlags(&eH2,   cudaEventDisableTiming);
    }
};
static StreamPack g_sp;

// ================= launch =================
static inline void* symaddr(const void* s) { void* p = nullptr; cudaGetSymbolAddress(&p, s); return p; }

extern "C" void kernel_launch(void* const* d_in, const int* in_sizes, int n_in,
                              void* d_out, int out_size)
{
    const float* x     = (const float*)d_in[0];
    const float* w     = (const float*)d_in[1];
    const float* ln1_g = (const float*)d_in[2];
    const float* ln1_b = (const float*)d_in[3];
    const float* ln2_g = (const float*)d_in[4];
    const float* ln2_b = (const float*)d_in[5];
    const float* g1_W  = (const float*)d_in[6];
    const float* g1_b  = (const float*)d_in[7];
    const float* s1_W  = (const float*)d_in[8];
    const float* s1_b  = (const float*)d_in[9];
    const float* m1_W  = (const float*)d_in[10];
    const float* m1_b  = (const float*)d_in[11];
    const float* g2_W  = (const float*)d_in[12];
    const float* g2_b  = (const float*)d_in[13];
    const float* s2_W  = (const float*)d_in[14];
    const float* s2_b  = (const float*)d_in[15];
    const float* m2_W  = (const float*)d_in[16];
    const float* m2_b  = (const float*)d_in[17];
    const float* gs_W  = (const float*)d_in[18];
    const float* gs_b  = (const float*)d_in[19];
    const float* ss_W  = (const float*)d_in[20];
    const float* ss_b  = (const float*)d_in[21];
    const float* ms_W  = (const float*)d_in[22];
    const float* ms_b  = (const float*)d_in[23];
    const float* r1_W  = (const float*)d_in[24];
    const float* r1_b  = (const float*)d_in[25];
    const float* r2_W  = (const float*)d_in[26];
    const float* r2_b  = (const float*)d_in[27];
    float* out = (float*)d_out;

    float* x2   = (float*)symaddr(g_x2);
    float* h1   = (float*)symaddr(g_h1);
    float* mix  = (float*)symaddr(g_mix);
    float* s12  = (float*)symaddr(g_s12);
    float* ssv  = (float*)symaddr(g_ss);
    float* zb   = (float*)symaddr(g_zero);
    float* bil  = (float*)symaddr(g_bil);
    __half* xh   = (__half*)symaddr(g_xh);
    __half* xl   = (__half*)symaddr(g_xl);
    __half* a12h = (__half*)symaddr(g_a12h);
    __half* a12l = (__half*)symaddr(g_a12l);
    __half* ash  = (__half*)symaddr(g_ash);
    __half* asl  = (__half*)symaddr(g_asl);
    __half* h2h  = (__half*)symaddr(g_h2h);
    __half* h2l  = (__half*)symaddr(g_h2l);
    __half* h1th = (__half*)symaddr(g_h1th);
    __half* h1tl = (__half*)symaddr(g_h1tl);
    __half* xTh  = (__half*)symaddr(g_xTh);
    __half* xTl  = (__half*)symaddr(g_xTl);
    __half* mTh  = (__half*)symaddr(g_mTh);
    __half* mTl  = (__half*)symaddr(g_mTl);
    __half* wTh  = (__half*)symaddr(g_wTh);
    __half* wTl  = (__half*)symaddr(g_wTl);
    __half* x3h  = (__half*)symaddr(g_x3h);
    __half* x3l  = (__half*)symaddr(g_x3l);

    cudaFuncSetAttribute(gemm_sp<0>, cudaFuncAttributeMaxDynamicSharedMemorySize, GSMEM_SZ);
    cudaFuncSetAttribute(gemm_sp<1>, cudaFuncAttributeMaxDynamicSharedMemorySize, GSMEM_SZ);
    cudaFuncSetAttribute(gemm_sp<2>, cudaFuncAttributeMaxDynamicSharedMemorySize, GSMEM_SZ);

    const dim3 tb(32, 8);
    cudaStream_t d = 0, s1 = g_sp.s1, s2 = g_sp.s2;

    // ---- fork ----
    cudaEventRecord(g_sp.eF, d);
    cudaStreamWaitEvent(s1, g_sp.eF, 0);
    cudaStreamWaitEvent(s2, g_sp.eF, 0);

    // d: LN1
    ln_split<<<MTOK, 256, 0, d>>>(x, ln1_g, ln1_b, xh, xl);
    cudaEventRecord(g_sp.eLN, d);

    // s1: prep, then xT transpose
    prep_small<<<597, 256, 0, s1>>>(w, s1_W, s1_b, s2_W, s2_b, ss_W, ss_b,
                                    g1_b, g2_b, gs_b, r1_b, s12, ssv, bil);
    cudaEventRecord(g_sp.ePrep, s1);
    cudaStreamWaitEvent(s1, g_sp.eLN, 0);
    transpose_hf2<<<dim3(Cc/32, Tt/32, Bb), tb, 0, s1>>>(xh, xl, xTh, xTl, Tt, Cc,
        (long long)Tt*Cc, (long long)Tt*Cc);
    cudaEventRecord(g_sp.eXT, s1);

    // s2: all weight transposes
    transpose_split_il2<<<dim3(H1h/32, Cc/32, 2), tb, 0, s2>>>(g1_W, g2_W, wTh + W0_OFF, wTl + W0_OFF);
    cudaEventRecord(g_sp.eW0, s2);
    transpose_split   <<<dim3(TDd/32, TDd/32, 1), tb, 0, s2>>>(m1_W, wTh + W1_OFF, wTl + W1_OFF, TDd, TDd, 0, 0);
    transpose_split   <<<dim3(TDd/32, TDd/32, 1), tb, 0, s2>>>(m2_W, wTh + W2_OFF, wTl + W2_OFF, TDd, TDd, 0, 0);
    transpose_split_il<<<dim3(CDd/32, Cc/32),     tb, 0, s2>>>(gs_W, wTh + W3_OFF, wTl + W3_OFF, Cc, CDd, CDd/2);
    transpose_split   <<<dim3(Cc/32, (CDd/2)/32, 1), tb, 0, s2>>>(ms_W, wTh + W4_OFF, wTl + W4_OFF, CDd/2, Cc, 0, 0);
    transpose_split_il<<<dim3(Cc/32, Cc/32),      tb, 0, s2>>>(r1_W, wTh + W5_OFF, wTl + W5_OFF, Cc, Cc, Cc/2);
    transpose_split   <<<dim3(Cc/32, (Cc/2)/32, 1), tb, 0, s2>>>(r2_W, wTh + W6_OFF, wTl + W6_OFF, Cc/2, Cc, 0, 0);
    cudaEventRecord(g_sp.eWall, s2);

    // d: big fused GLU GEMM
    cudaStreamWaitEvent(d, g_sp.ePrep, 0);
    cudaStreamWaitEvent(d, g_sp.eW0, 0);
    gemm_sp<2><<<dim3(2*H1h/128, MTOK/128, 1), 256, GSMEM_SZ, d>>>(
        xh, xl, wTh + W0_OFF, wTl + W0_OFF, nullptr, a12h, a12l, bil,
        nullptr, nullptr, nullptr, s12, H1h, MTOK, 2*H1h, Cc, Cc, 0, 0, 0, 0);
    cudaEventRecord(g_sp.eA12, d);
    cudaStreamWaitEvent(d, g_sp.eWall, 0);

    // s1: m2 GEMM
    cudaStreamWaitEvent(s1, g_sp.eA12, 0);
    cudaStreamWaitEvent(s1, g_sp.eWall, 0);
    gemm_sp<0><<<dim3(TDd/128, MTOK/128, 1), 256, GSMEM_SZ, s1>>>(
        a12h + TDd, a12l + TDd, wTh + W2_OFF, wTl + W2_OFF, nullptr, h2h, h2l, m2_b,
        nullptr, nullptr, nullptr, nullptr, 0, MTOK, TDd, TDd, H1h, 0, 0, 0, 0);
    cudaEventRecord(g_sp.eH2, s1);

    // d: m1 -> h1t -> mix -> mT
    gemm_sp<0><<<dim3(TDd/128, MTOK/128, 1), 256, GSMEM_SZ, d>>>(
        a12h, a12l, wTh + W1_OFF, wTl + W1_OFF, h1, nullptr, nullptr, m1_b,
        nullptr, nullptr, nullptr, nullptr, 0, MTOK, TDd, TDd, H1h, 0, 0, 0, 0);
    transpose_split<<<dim3(TDd/32, Tt/32, Bb), tb, 0, d>>>(h1, h1th, h1tl, Tt, TDd,
        (long long)Tt*TDd, (long long)Tt*TDd);
    cudaStreamWaitEvent(d, g_sp.eXT, 0);
    gemm_sp<1><<<dim3(Cc/128, TDd/128, Bb), 256, GSMEM_SZ, d>>>(
        h1th, h1tl, xTh, xTl, mix, nullptr, nullptr, zb,
        nullptr, nullptr, nullptr, nullptr, 0,
        TDd, Cc, Tt, Tt, (long long)TDd*Tt, (long long)Cc*Tt, (long long)TDd*Cc, 0);
    transpose_split<<<dim3(Cc/32, TDd/32, Bb), tb, 0, d>>>(mix, mTh, mTl, TDd, Cc,
        (long long)TDd*Cc, (long long)TDd*Cc);

    // d: x2 = xln + h2 @ mix (join s1)
    cudaStreamWaitEvent(d, g_sp.eH2, 0);
    gemm_sp<0><<<dim3(Cc/128, Tt/128, Bb), 256, GSMEM_SZ, d>>>(
        h2h, h2l, mTh, mTl, x2, nullptr, nullptr, zb, nullptr, xh, xl, nullptr, 0,
        Tt, Cc, TDd, TDd, (long long)Tt*TDd, (long long)Cc*TDd, (long long)Tt*Cc, (long long)Tt*Cc);

    // d: LN2 -> gs -> ms -> head
    ln_split<<<MTOK, 256, 0, d>>>(x2, ln2_g, ln2_b, xh, xl);
    gemm_sp<2><<<dim3(CDd/128, MTOK/128, 1), 256, GSMEM_SZ, d>>>(
        xh, xl, wTh + W3_OFF, wTl + W3_OFF, nullptr, ash, asl, bil + 1536,
        nullptr, nullptr, nullptr, ssv, CDd/2, MTOK, CDd, Cc, Cc, 0, 0, 0, 0);
    gemm_sp<0><<<dim3(Cc/128, MTOK/128, 1), 256, GSMEM_SZ, d>>>(
        ash, asl, wTh + W4_OFF, wTl + W4_OFF, x2, x3h, x3l, ms_b, x2,
        nullptr, nullptr, nullptr, 0, MTOK, Cc, CDd/2, CDd/2, 0, 0, 0, 0);
    gemm_sp<2><<<dim3(Cc/128, MTOK/128, 1), 256, GSMEM_SZ, d>>>(
        x3h, x3l, wTh + W5_OFF, wTl + W5_OFF, nullptr, a12h, a12l, bil + 4608,
        nullptr, nullptr, nullptr, nullptr, 0, MTOK, Cc, Cc, Cc, 0, 0, 0, 0);
    gemm_sp<0><<<dim3(Cc/128, MTOK/128, 1), 256, GSMEM_SZ, d>>>(
        a12h, a12l, wTh + W6_OFF, wTl + W6_OFF, out, nullptr, nullptr, r2_b,
        nullptr, nullptr, nullptr, nullptr, 0, MTOK, Cc, Cc/2, Cc/2, 0, 0, 0, 0);
}

// round 14
// speedup vs baseline: 1.2146x; 1.2146x over previous
#include <cuda_runtime.h>
#include <cuda_fp16.h>
#include <cstdint>
#include <math.h>

// ---------------- problem constants ----------------
#define Bb   8
#define Tt   2048
#define Cc   768
#define WDd  512
#define TDd  384
#define CDd  3072
#define H1h  768
#define MTOK (Bb * Tt)          // 16384

// ---------------- fp32 scratch ----------------
__device__ float g_x2 [MTOK * Cc];
__device__ float g_h1 [MTOK * TDd];
__device__ float g_mix[Bb * TDd * Cc];
__device__ float g_s12[Bb * H1h];
__device__ float g_ss [Bb * (CDd/2)];
__device__ float g_zero[CDd];
__device__ float g_bil[6144];
__device__ float g_xtf [MTOK * Cc];         // LN2 out, tf32-rounded
__device__ float g_astf[MTOK * (CDd/2)];    // gs GLU out, tf32-rounded
__device__ float g_wgs [CDd * Cc];          // gs_W transposed+interleaved, tf32
__device__ float g_wms [Cc * (CDd/2)];      // ms_W transposed, tf32

// ---------------- fp16 split operand buffers ----------------
__device__ __half g_xh [MTOK*Cc],        g_xl [MTOK*Cc];
__device__ __half g_a12h[MTOK*H1h],      g_a12l[MTOK*H1h];
__device__ __half g_h2h[MTOK*TDd],       g_h2l[MTOK*TDd];
__device__ __half g_h1th[Bb*TDd*Tt],     g_h1tl[Bb*TDd*Tt];
__device__ __half g_xTh[Bb*Cc*Tt],       g_xTl[Bb*Cc*Tt];
__device__ __half g_mTh[Bb*Cc*TDd],      g_mTl[Bb*Cc*TDd];
__device__ __half g_x3h[MTOK*Cc],        g_x3l[MTOK*Cc];

// fp16 transposed-weight slices (hi/lo): W0 g1|g2 il, W1 m1, W2 m2, W5 r1 il, W6 r2
#define W0_OFF 0
#define W1_OFF (W0_OFF + 2*H1h*Cc)
#define W2_OFF (W1_OFF + TDd*TDd)
#define W5_OFF (W2_OFF + TDd*TDd)
#define W6_OFF (W5_OFF + Cc*Cc)
#define W_TOT  (W6_OFF + (Cc/2)*Cc)
__device__ __half g_wTh[W_TOT], g_wTl[W_TOT];

// ---------------- helpers ----------------
__device__ __forceinline__ uint32_t smem_u32(const void* p) {
    uint32_t a;
    asm("{ .reg .u64 t; cvta.to.shared.u64 t, %1; cvt.u32.u64 %0, t; }" : "=r"(a) : "l"(p));
    return a;
}
__device__ __forceinline__ void cpa16(uint32_t s, const void* g) {
    asm volatile("cp.async.cg.shared.global [%0], [%1], 16;" :: "r"(s), "l"(g));
}
__device__ __forceinline__ void ldsm4(uint32_t& r0, uint32_t& r1, uint32_t& r2, uint32_t& r3,
                                      uint32_t a) {
    asm volatile("ldmatrix.sync.aligned.m8n8.x4.shared.b16 {%0,%1,%2,%3}, [%4];"
                 : "=r"(r0), "=r"(r1), "=r"(r2), "=r"(r3) : "r"(a));
}
__device__ __forceinline__ void mma_f16(float* c, const uint32_t* a,
                                        uint32_t b0, uint32_t b1) {
    asm volatile(
        "mma.sync.aligned.m16n8k16.row.col.f32.f16.f16.f32 "
        "{%0,%1,%2,%3}, {%4,%5,%6,%7}, {%8,%9}, {%0,%1,%2,%3};"
        : "+f"(c[0]), "+f"(c[1]), "+f"(c[2]), "+f"(c[3])
        : "r"(a[0]), "r"(a[1]), "r"(a[2]), "r"(a[3]), "r"(b0), "r"(b1));
}
__device__ __forceinline__ void mma_tf32(float* c, const uint32_t* a,
                                         uint32_t b0, uint32_t b1) {
    asm volatile(
        "mma.sync.aligned.m16n8k8.row.col.f32.tf32.tf32.f32 "
        "{%0,%1,%2,%3}, {%4,%5,%6,%7}, {%8,%9}, {%0,%1,%2,%3};"
        : "+f"(c[0]), "+f"(c[1]), "+f"(c[2]), "+f"(c[3])
        : "r"(a[0]), "r"(a[1]), "r"(a[2]), "r"(a[3]), "r"(b0), "r"(b1));
}
__device__ __forceinline__ void split_one(float v, __half& h, __half& l) {
    h = __float2half_rn(v);
    l = __float2half_rn(v - __half2float(h));
}
__device__ __forceinline__ float f2tf(float f) {
    uint32_t u;
    asm("cvt.rna.tf32.f32 %0, %1;" : "=r"(u) : "f"(f));
    return __uint_as_float(u);
}

// ================= split-fp16 GEMM: BK=32, 2-stage cp.async (R12 shape) ==========
// ACT: 0=bias(+res), 1=gelu, 2=GLU-pairs (interleaved weights; out N/2 cols)
#define LDBB 80
#define TILE_B (128 * LDBB)
#define GSMEM_SZ (8 * TILE_B)

template <int ACT>
__global__ void __launch_bounds__(256, 2) gemm_sp(
    const __half* __restrict__ Ah_, const __half* __restrict__ Al_,
    const __half* __restrict__ Bh_, const __half* __restrict__ Bl_,
    float* __restrict__ Cf, __half* __restrict__ Ch, __half* __restrict__ Cl,
    const float* __restrict__ bias, const float* __restrict__ resF,
    const __half* __restrict__ resH, const __half* __restrict__ resL,
    const float* __restrict__ scale, int sN,
    int M, int N, int K, int lda,
    long long sA, long long sB, long long sC, long long sR)
{
    extern __shared__ char smem[];
    const uint32_t sbase = smem_u32(smem);
    const int tid = threadIdx.x, wid = tid >> 5, lane = tid & 31;
    const int g = lane >> 2, tg = lane & 3;
    const int wm = (wid >> 1) * 32;
    const int wn = (wid & 1) * 64;

    const int bz = blockIdx.z;
    const long long ldaB = (long long)lda * 2;
    const long long ldbB = (long long)K * 2;

    const int row0 = blockIdx.y * 128;
    const int col0 = blockIdx.x * 128;

    const char* Agh = (const char*)(Ah_ + bz * sA) + (long long)row0 * ldaB;
    const char* Agl = (const char*)(Al_ + bz * sA) + (long long)row0 * ldaB;
    const char* Bgh = (const char*)(Bh_ + bz * sB) + (long long)col0 * ldbB;
    const char* Bgl = (const char*)(Bl_ + bz * sB) + (long long)col0 * ldbB;
    if (Cf) Cf += bz * sC;
    if (Ch) { Ch += bz * sC; Cl += bz * sC; }
    if (resF) resF += bz * sR;
    if (resH) { resH += bz * sR; resL += bz * sR; }

    const int nIter = K >> 5;
    const int rr = tid >> 2;
    const int cbo = (tid & 3) * 16;

    auto issue = [&](int i) {
        const uint32_t sb0 = sbase + (uint32_t)(i & 1) * 4 * TILE_B;
        const long long ko = (long long)i * 64;
#pragma unroll
        for (int t = 0; t < 2; t++) {
            const int r = rr + t * 64;
            const uint32_t so = (uint32_t)r * LDBB + cbo;
            cpa16(sb0 + so,              Agh + (long long)r * ldaB + ko + cbo);
            cpa16(sb0 + TILE_B + so,     Agl + (long long)r * ldaB + ko + cbo);
            cpa16(sb0 + 2 * TILE_B + so, Bgh + (long long)r * ldbB + ko + cbo);
            cpa16(sb0 + 3 * TILE_B + so, Bgl + (long long)r * ldbB + ko + cbo);
        }
    };

    issue(0); asm volatile("cp.async.commit_group;");
    issue(1); asm volatile("cp.async.commit_group;");

    const uint32_t aOff0 = (uint32_t)(wm + (lane & 7) + ((lane >> 3) & 1) * 8) * LDBB
                         + (uint32_t)(lane >> 4) * 16;
    const uint32_t aOff1 = aOff0 + 16 * LDBB;
    const uint32_t bOff0 = (uint32_t)(wn + (lane & 7) + (lane >> 4) * 8) * LDBB
                         + (uint32_t)((lane >> 3) & 1) * 16;

    float acc[2][8][4];
#pragma unroll
    for (int mt = 0; mt < 2; mt++)
#pragma unroll
        for (int nt = 0; nt < 8; nt++)
#pragma unroll
            for (int q = 0; q < 4; q++) acc[mt][nt][q] = 0.f;

    for (int i = 0; i < nIter; i++) {
        asm volatile("cp.async.wait_group 1;");
        __syncthreads();
        const uint32_t st = sbase + (uint32_t)(i & 1) * 4 * TILE_B;
#pragma unroll
        for (int kk = 0; kk < 2; kk++) {
            const uint32_t kb = kk * 32;
            uint32_t ah[2][4], al[2][4];
            ldsm4(ah[0][0], ah[0][1], ah[0][2], ah[0][3], st + aOff0 + kb);
            ldsm4(ah[1][0], ah[1][1], ah[1][2], ah[1][3], st + aOff1 + kb);
            ldsm4(al[0][0], al[0][1], al[0][2], al[0][3], st + TILE_B + aOff0 + kb);
            ldsm4(al[1][0], al[1][1], al[1][2], al[1][3], st + TILE_B + aOff1 + kb);
            {
                uint32_t bh[4][4];
#pragma unroll
                for (int ntp = 0; ntp < 4; ntp++)
                    ldsm4(bh[ntp][0], bh[ntp][1], bh[ntp][2], bh[ntp][3],
                          st + 2 * TILE_B + bOff0 + (uint32_t)ntp * 16 * LDBB + kb);
#pragma unroll
                for (int ntp = 0; ntp < 4; ntp++) {
                    const int n0 = 2 * ntp, n1 = 2 * ntp + 1;
                    mma_f16(acc[0][n0], ah[0], bh[ntp][0], bh[ntp][1]);
                    mma_f16(acc[1][n0], ah[1], bh[ntp][0], bh[ntp][1]);
                    mma_f16(acc[0][n1], ah[0], bh[ntp][2], bh[ntp][3]);
                    mma_f16(acc[1][n1], ah[1], bh[ntp][2], bh[ntp][3]);
                }
#pragma unroll
                for (int ntp = 0; ntp < 4; ntp++) {
                    const int n0 = 2 * ntp, n1 = 2 * ntp + 1;
                    mma_f16(acc[0][n0], al[0], bh[ntp][0], bh[ntp][1]);
                    mma_f16(acc[1][n0], al[1], bh[ntp][0], bh[ntp][1]);
                    mma_f16(acc[0][n1], al[0], bh[ntp][2], bh[ntp][3]);
                    mma_f16(acc[1][n1], al[1], bh[ntp][2], bh[ntp][3]);
                }
            }
            {
                uint32_t bl[4][4];
#pragma unroll
                for (int ntp = 0; ntp < 4; ntp++)
                    ldsm4(bl[ntp][0], bl[ntp][1], bl[ntp][2], bl[ntp][3],
                          st + 3 * TILE_B + bOff0 + (uint32_t)ntp * 16 * LDBB + kb);
#pragma unroll
                for (int ntp = 0; ntp < 4; ntp++) {
                    const int n0 = 2 * ntp, n1 = 2 * ntp + 1;
                    mma_f16(acc[0][n0], ah[0], bl[ntp][0], bl[ntp][1]);
                    mma_f16(acc[1][n0], ah[1], bl[ntp][0], bl[ntp][1]);
                    mma_f16(acc[0][n1], ah[0], bl[ntp][2], bl[ntp][3]);
                    mma_f16(acc[1][n1], ah[1], bl[ntp][2], bl[ntp][3]);
                }
            }
        }
        __syncthreads();
        if (i + 2 < nIter) issue(i + 2);
        asm volatile("cp.async.commit_group;");
    }
    asm volatile("cp.async.wait_all;");

    const int Nout = (ACT == 2) ? (N >> 1) : N;
#pragma unroll
    for (int mt = 0; mt < 2; mt++) {
        const int r = row0 + wm + mt * 16 + g;
#pragma unroll
        for (int nt = 0; nt < 8; nt++) {
            const int c = col0 + wn + nt * 8 + tg * 2;
            const float bx = __ldg(&bias[c]), by = __ldg(&bias[c + 1]);
            float v0 = acc[mt][nt][0] + bx;
            float v1 = acc[mt][nt][1] + by;
            float v2 = acc[mt][nt][2] + bx;
            float v3 = acc[mt][nt][3] + by;
            if (ACT == 2) {
                const int c2 = c >> 1;
                float o0 = v0 / (1.0f + __expf(-v1));
                float o1 = v2 / (1.0f + __expf(-v3));
                if (scale) {
                    o0 *= __ldg(&scale[(r / Tt) * sN + c2]);
                    o1 *= __ldg(&scale[((r + 8) / Tt) * sN + c2]);
                }
                __half h0, l0, h1, l1;
                split_one(o0, h0, l0); split_one(o1, h1, l1);
                Ch[(long long)r * Nout + c2] = h0;
                Cl[(long long)r * Nout + c2] = l0;
                Ch[(long long)(r + 8) * Nout + c2] = h1;
                Cl[(long long)(r + 8) * Nout + c2] = l1;
            } else {
                if (resF) {
                    const float2 r0 = *(const float2*)(resF + (long long)r * N + c);
                    const float2 r1 = *(const float2*)(resF + (long long)(r + 8) * N + c);
                    v0 += r0.x; v1 += r0.y; v2 += r1.x; v3 += r1.y;
                }
                if (resH) {
                    const __half2 h0 = *(const __half2*)(resH + (long long)r * N + c);
                    const __half2 l0 = *(const __half2*)(resL + (long long)r * N + c);
                    const __half2 h1 = *(const __half2*)(resH + (long long)(r + 8) * N + c);
                    const __half2 l1 = *(const __half2*)(resL + (long long)(r + 8) * N + c);
                    v0 += __half2float(h0.x) + __half2float(l0.x);
                    v1 += __half2float(h0.y) + __half2float(l0.y);
                    v2 += __half2float(h1.x) + __half2float(l1.x);
                    v3 += __half2float(h1.y) + __half2float(l1.y);
                }
                if (ACT == 1) {
                    v0 = 0.5f * v0 * (1.0f + erff(v0 * 0.70710678118654752f));
                    v1 = 0.5f * v1 * (1.0f + erff(v1 * 0.70710678118654752f));
                    v2 = 0.5f * v2 * (1.0f + erff(v2 * 0.70710678118654752f));
                    v3 = 0.5f * v3 * (1.0f + erff(v3 * 0.70710678118654752f));
                }
                if (Cf) {
                    *(float2*)(Cf + (long long)r * N + c)       = make_float2(v0, v1);
                    *(float2*)(Cf + (long long)(r + 8) * N + c) = make_float2(v2, v3);
                }
                if (Ch) {
                    __half2 h01, l01, h23, l23;
                    split_one(v0, h01.x, l01.x); split_one(v1, h01.y, l01.y);
                    split_one(v2, h23.x, l23.x); split_one(v3, h23.y, l23.y);
                    *(__half2*)(Ch + (long long)r * N + c)       = h01;
                    *(__half2*)(Cl + (long long)r * N + c)       = l01;
                    *(__half2*)(Ch + (long long)(r + 8) * N + c) = h23;
                    *(__half2*)(Cl + (long long)(r + 8) * N + c) = l23;
                }
            }
        }
    }
}

// ================= single-pass tf32 GEMM: BK=32, 2-stage cp.async ================
// A [M][lda] fp32 (tf32-prerounded), B [N][K] fp32 (tf32-prerounded).
// ACT2: GLU pairs -> tf32 fp32 out [M][N/2] (*scale). ACT0: bias+resF -> Cf + fp16 split.
#define TFW 36
#define TFTILE_B (128 * TFW * 4)          // 18432
#define TFSMEM_SZ (4 * TFTILE_B)          // 73728

template <int ACT>
__global__ void __launch_bounds__(256, 2) gemm_tf(
    const float* __restrict__ A_, const float* __restrict__ B_,
    float* __restrict__ Cf, float* __restrict__ Ctf,
    __half* __restrict__ Ch, __half* __restrict__ Cl,
    const float* __restrict__ bias, const float* __restrict__ resF,
    const float* __restrict__ scale, int sN,
    int M, int N, int K, int lda)
{
    extern __shared__ char smem[];
    const uint32_t sbase = smem_u32(smem);
    const int tid = threadIdx.x, wid = tid >> 5, lane = tid & 31;
    const int g = lane >> 2, tg = lane & 3;
    const int wm = (wid >> 1) * 32;
    const int wn = (wid & 1) * 64;

    const long long ldaB = (long long)lda * 4;
    const long long ldbB = (long long)K * 4;

    const int row0 = blockIdx.y * 128;
    const int col0 = blockIdx.x * 128;
    const char* Ag = (const char*)A_ + (long long)row0 * ldaB;
    const char* Bg = (const char*)B_ + (long long)col0 * ldbB;

    const int nIter = K >> 5;

    auto issue = [&](int i) {
        const uint32_t sb0 = sbase + (uint32_t)(i & 1) * 2 * TFTILE_B;
        const long long ko = (long long)i * 128;    // 32 floats
#pragma unroll
        for (int q = 0; q < 4; q++) {
            const int ch = tid + q * 256;           // 0..1023
            const int r = ch >> 3;
            const uint32_t cb = (uint32_t)(ch & 7) * 16;
            const uint32_t so = (uint32_t)r * (TFW * 4) + cb;
            cpa16(sb0 + so,            Ag + (long long)r * ldaB + ko + cb);
            cpa16(sb0 + TFTILE_B + so, Bg + (long long)r * ldbB + ko + cb);
        }
    };

    issue(0); asm volatile("cp.async.commit_group;");
    issue(1); asm volatile("cp.async.commit_group;");

    float acc[2][8][4];
#pragma unroll
    for (int mt = 0; mt < 2; mt++)
#pragma unroll
        for (int nt = 0; nt < 8; nt++)
#pragma unroll
            for (int q = 0; q < 4; q++) acc[mt][nt][q] = 0.f;

    for (int i = 0; i < nIter; i++) {
        asm volatile("cp.async.wait_group 1;");
        __syncthreads();
        const float* As = (const float*)(smem + (size_t)(i & 1) * 2 * TFTILE_B);
        const float* Bs = As + TFW * 128;
#pragma unroll
        for (int kk = 0; kk < 4; kk++) {
            const int k0 = kk * 8;
            uint32_t af[2][4];
#pragma unroll
            for (int mt = 0; mt < 2; mt++) {
                const int rm = wm + mt * 16;
                af[mt][0] = __float_as_uint(As[(rm + g) * TFW + k0 + tg]);
                af[mt][1] = __float_as_uint(As[(rm + 8 + g) * TFW + k0 + tg]);
                af[mt][2] = __float_as_uint(As[(rm + g) * TFW + k0 + tg + 4]);
                af[mt][3] = __float_as_uint(As[(rm + 8 + g) * TFW + k0 + tg + 4]);
            }
#pragma unroll
            for (int nt = 0; nt < 8; nt++) {
                const int cn = wn + nt * 8;
                const uint32_t b0 = __float_as_uint(Bs[(cn + g) * TFW + k0 + tg]);
                const uint32_t b1 = __float_as_uint(Bs[(cn + g) * TFW + k0 + tg + 4]);
                mma_tf32(acc[0][nt], af[0], b0, b1);
                mma_tf32(acc[1][nt], af[1], b0, b1);
            }
        }
        __syncthreads();
        if (i + 2 < nIter) issue(i + 2);
        asm volatile("cp.async.commit_group;");
    }
    asm volatile("cp.async.wait_all;");

    const int Nout = (ACT == 2) ? (N >> 1) : N;
#pragma unroll
    for (int mt = 0; mt < 2; mt++) {
        const int r = row0 + wm + mt * 16 + g;
#pragma unroll
        for (int nt = 0; nt < 8; nt++) {
            const int c = col0 + wn + nt * 8 + tg * 2;
            const float bx = __ldg(&bias[c]), by = __ldg(&bias[c + 1]);
            float v0 = acc[mt][nt][0] + bx;
            float v1 = acc[mt][nt][1] + by;
            float v2 = acc[mt][nt][2] + bx;
            float v3 = acc[mt][nt][3] + by;
            if (ACT == 2) {
                const int c2 = c >> 1;
                float o0 = v0 / (1.0f + __expf(-v1));
                float o1 = v2 / (1.0f + __expf(-v3));
                if (scale) {
                    o0 *= __ldg(&scale[(r / Tt) * sN + c2]);
                    o1 *= __ldg(&scale[((r + 8) / Tt) * sN + c2]);
                }
                Ctf[(long long)r * Nout + c2]       = f2tf(o0);
                Ctf[(long long)(r + 8) * Nout + c2] = f2tf(o1);
            } else {
                if (resF) {
                    const float2 r0 = *(const float2*)(resF + (long long)r * N + c);
                    const float2 r1 = *(const float2*)(resF + (long long)(r + 8) * N + c);
                    v0 += r0.x; v1 += r0.y; v2 += r1.x; v3 += r1.y;
                }
                if (Cf) {
                    *(float2*)(Cf + (long long)r * N + c)       = make_float2(v0, v1);
                    *(float2*)(Cf + (long long)(r + 8) * N + c) = make_float2(v2, v3);
                }
                if (Ch) {
                    __half2 h01, l01, h23, l23;
                    split_one(v0, h01.x, l01.x); split_one(v1, h01.y, l01.y);
                    split_one(v2, h23.x, l23.x); split_one(v3, h23.y, l23.y);
                    *(__half2*)(Ch + (long long)r * N + c)       = h01;
                    *(__half2*)(Cl + (long long)r * N + c)       = l01;
                    *(__half2*)(Ch + (long long)(r + 8) * N + c) = h23;
                    *(__half2*)(Cl + (long long)(r + 8) * N + c) = l23;
                }
            }
        }
    }
}

// ================= transposes =================
__global__ void transpose_split(const float* __restrict__ in,
                                __half* __restrict__ oh, __half* __restrict__ ol,
                                int R, int Cn, long long sIn, long long sOut)
{
    __shared__ float t[32][33];
    const int bz = blockIdx.z;
    in += bz * sIn; oh += bz * sOut; ol += bz * sOut;
    const int c0 = blockIdx.x * 32, r0 = blockIdx.y * 32;
    const int x = threadIdx.x, y = threadIdx.y;
#pragma unroll
    for (int dy = 0; dy < 32; dy += 8)
        t[y + dy][x] = in[(long long)(r0 + y + dy) * Cn + c0 + x];
    __syncthreads();
#pragma unroll
    for (int dy = 0; dy < 32; dy += 8) {
        __half h, l;
        split_one(t[x][y + dy], h, l);
        const long long o = (long long)(c0 + y + dy) * R + r0 + x;
        oh[o] = h; ol[o] = l;
    }
}

__global__ void transpose_hf2(const __half* __restrict__ ih, const __half* __restrict__ il,
                              __half* __restrict__ oh, __half* __restrict__ ol,
                              int R, int Cn, long long sIn, long long sOut)
{
    __shared__ __half th[32][34];
    __shared__ __half tl[32][34];
    const int bz = blockIdx.z;
    ih += bz * sIn; il += bz * sIn; oh += bz * sOut; ol += bz * sOut;
    const int c0 = blockIdx.x * 32, r0 = blockIdx.y * 32;
    const int x = threadIdx.x, y = threadIdx.y;
#pragma unroll
    for (int dy = 0; dy < 32; dy += 8) {
        const long long o = (long long)(r0 + y + dy) * Cn + c0 + x;
        th[y + dy][x] = ih[o];
        tl[y + dy][x] = il[o];
    }
    __syncthreads();
#pragma unroll
    for (int dy = 0; dy < 32; dy += 8) {
        const long long o = (long long)(c0 + y + dy) * R + r0 + x;
        oh[o] = th[x][y + dy];
        ol[o] = tl[x][y + dy];
    }
}

__global__ void transpose_split_il(const float* __restrict__ in,
                                   __half* __restrict__ oh, __half* __restrict__ ol,
                                   int R, int Cn, int Hhalf)
{
    __shared__ float t[32][33];
    const int c0 = blockIdx.x * 32, r0 = blockIdx.y * 32;
    const int x = threadIdx.x, y = threadIdx.y;
#pragma unroll
    for (int dy = 0; dy < 32; dy += 8)
        t[y + dy][x] = in[(long long)(r0 + y + dy) * Cn + c0 + x];
    __syncthreads();
#pragma unroll
    for (int dy = 0; dy < 32; dy += 8) {
        const int c = c0 + y + dy;
        const int dr = (c < Hhalf) ? 2 * c : 2 * (c - Hhalf) + 1;
        __half h, l;
        split_one(t[x][y + dy], h, l);
        const long long o = (long long)dr * R + r0 + x;
        oh[o] = h; ol[o] = l;
    }
}

__global__ void transpose_split_il2(const float* __restrict__ g1W,
                                    const float* __restrict__ g2W,
                                    __half* __restrict__ oh, __half* __restrict__ ol)
{
    __shared__ float t[32][33];
    const float* in = blockIdx.z ? g2W : g1W;
    const long long dofs = blockIdx.z ? (long long)H1h * Cc : 0;
    const int c0 = blockIdx.x * 32, r0 = blockIdx.y * 32;
    const int x = threadIdx.x, y = threadIdx.y;
#pragma unroll
    for (int dy = 0; dy < 32; dy += 8)
        t[y + dy][x] = in[(long long)(r0 + y + dy) * H1h + c0 + x];
    __syncthreads();
#pragma unroll
    for (int dy = 0; dy < 32; dy += 8) {
        const int c = c0 + y + dy;
        const int dr = (c < H1h/2) ? 2 * c : 2 * (c - H1h/2) + 1;
        __half h, l;
        split_one(t[x][y + dy], h, l);
        const long long o = dofs + (long long)dr * Cc + r0 + x;
        oh[o] = h; ol[o] = l;
    }
}

// tf32 weight transposes
__global__ void transpose_tf(const float* __restrict__ in, float* __restrict__ o,
                             int R, int Cn)
{
    __shared__ float t[32][33];
    const int c0 = blockIdx.x * 32, r0 = blockIdx.y * 32;
    const int x = threadIdx.x, y = threadIdx.y;
#pragma unroll
    for (int dy = 0; dy < 32; dy += 8)
        t[y + dy][x] = in[(long long)(r0 + y + dy) * Cn + c0 + x];
    __syncthreads();
#pragma unroll
    for (int dy = 0; dy < 32; dy += 8)
        o[(long long)(c0 + y + dy) * R + r0 + x] = f2tf(t[x][y + dy]);
}

__global__ void transpose_tf_il(const float* __restrict__ in, float* __restrict__ o,
                                int R, int Cn, int Hhalf)
{
    __shared__ float t[32][33];
    const int c0 = blockIdx.x * 32, r0 = blockIdx.y * 32;
    const int x = threadIdx.x, y = threadIdx.y;
#pragma unroll
    for (int dy = 0; dy < 32; dy += 8)
        t[y + dy][x] = in[(long long)(r0 + y + dy) * Cn + c0 + x];
    __syncthreads();
#pragma unroll
    for (int dy = 0; dy < 32; dy += 8) {
        const int c = c0 + y + dy;
        const int dr = (c < Hhalf) ? 2 * c : 2 * (c - Hhalf) + 1;
        o[(long long)dr * R + r0 + x] = f2tf(t[x][y + dy]);
    }
}

// ================= LayerNorms =================
__global__ __launch_bounds__(256) void ln_split(const float* __restrict__ x,
                                                const float* __restrict__ g,
                                                const float* __restrict__ b,
                                                __half* __restrict__ oh,
                                                __half* __restrict__ ol)
{
    const int row = blockIdx.x;
    const float* xr = x + (long long)row * Cc;
    const int tid = threadIdx.x;
    float v0 = xr[tid], v1 = xr[tid + 256], v2 = xr[tid + 512];
    float s = v0 + v1 + v2;
    float q = v0 * v0 + v1 * v1 + v2 * v2;
    for (int off = 16; off > 0; off >>= 1) {
        s += __shfl_down_sync(0xffffffff, s, off);
        q += __shfl_down_sync(0xffffffff, q, off);
    }
    __shared__ float ssm[8], sqm[8];
    const int wid = tid >> 5, lid = tid & 31;
    if (lid == 0) { ssm[wid] = s; sqm[wid] = q; }
    __syncthreads();
    if (tid < 8) { s = ssm[tid]; q = sqm[tid]; }
    if (wid == 0) {
        for (int off = 4; off > 0; off >>= 1) {
            s += __shfl_down_sync(0x000000ff, s, off);
            q += __shfl_down_sync(0x000000ff, q, off);
        }
        if (tid == 0) { ssm[0] = s; sqm[0] = q; }
    }
    __syncthreads();
    const float mu  = ssm[0] * (1.0f / Cc);
    const float var = sqm[0] * (1.0f / Cc) - mu * mu;
    const float rs  = rsqrtf(var + 1e-6f);
#pragma unroll
    for (int t = 0; t < 3; t++) {
        const int j = tid + t * 256;
        const float vv = t == 0 ? v0 : (t == 1 ? v1 : v2);
        const float v = (vv - mu) * rs * g[j] + b[j];
        const long long o = (long long)row * Cc + j;
        __half h, l;
        split_one(v, h, l);
        oh[o] = h; ol[o] = l;
    }
}

__global__ __launch_bounds__(256) void ln_tf(const float* __restrict__ x,
                                             const float* __restrict__ g,
                                             const float* __restrict__ b,
                                             float* __restrict__ o)
{
    const int row = blockIdx.x;
    const float* xr = x + (long long)row * Cc;
    const int tid = threadIdx.x;
    float v0 = xr[tid], v1 = xr[tid + 256], v2 = xr[tid + 512];
    float s = v0 + v1 + v2;
    float q = v0 * v0 + v1 * v1 + v2 * v2;
    for (int off = 16; off > 0; off >>= 1) {
        s += __shfl_down_sync(0xffffffff, s, off);
        q += __shfl_down_sync(0xffffffff, q, off);
    }
    __shared__ float ssm[8], sqm[8];
    const int wid = tid >> 5, lid = tid & 31;
    if (lid == 0) { ssm[wid] = s; sqm[wid] = q; }
    __syncthreads();
    if (tid < 8) { s = ssm[tid]; q = sqm[tid]; }
    if (wid == 0) {
        for (int off = 4; off > 0; off >>= 1) {
            s += __shfl_down_sync(0x000000ff, s, off);
            q += __shfl_down_sync(0x000000ff, q, off);
        }
        if (tid == 0) { ssm[0] = s; sqm[0] = q; }
    }
    __syncthreads();
    const float mu  = ssm[0] * (1.0f / Cc);
    const float var = sqm[0] * (1.0f / Cc) - mu * mu;
    const float rs  = rsqrtf(var + 1e-6f);
#pragma unroll
    for (int t = 0; t < 3; t++) {
        const int j = tid + t * 256;
        const float vv = t == 0 ? v0 : (t == 1 ? v1 : v2);
        o[(long long)row * Cc + j] = f2tf((vv - mu) * rs * g[j] + b[j]);
    }
}

// ================= all small prep in ONE launch =================
__global__ __launch_bounds__(256) void prep_small(
    const float* __restrict__ w,
    const float* __restrict__ s1_W, const float* __restrict__ s1_b,
    const float* __restrict__ s2_W, const float* __restrict__ s2_b,
    const float* __restrict__ ss_W, const float* __restrict__ ss_b,
    const float* __restrict__ g1_b, const float* __restrict__ g2_b,
    const float* __restrict__ gs_b, const float* __restrict__ r1_b,
    float* __restrict__ s12, float* __restrict__ ssv, float* __restrict__ bil)
{
    const int blk = blockIdx.x;
    if (blk < 576) {
        const float* W; const float* bias; float* out; int N, ldout, b, n0;
        const float* wr;
        if (blk < 96)       { const int i = blk;       b = i / 12; n0 = (i % 12) * 32; W = s1_W; bias = s1_b; out = s12;           N = TDd;   ldout = H1h;   wr = w + (long long)b * 2 * WDd; }
        else if (blk < 192) { const int i = blk - 96;  b = i / 12; n0 = (i % 12) * 32; W = s2_W; bias = s2_b; out = s12 + TDd;     N = TDd;   ldout = H1h;   wr = w + (long long)b * 2 * WDd; }
        else                { const int i = blk - 192; b = i / 48; n0 = (i % 48) * 32; W = ss_W; bias = ss_b; out = ssv;           N = CDd/2; ldout = CDd/2; wr = w + (long long)b * 2 * WDd + WDd; }
        __shared__ float ws[WDd];
        __shared__ float red[8][32];
        for (int k = threadIdx.x; k < WDd; k += 256) ws[k] = wr[k];
        __syncthreads();
        const int lane = threadIdx.x & 31, sct = threadIdx.x >> 5;
        const int n = n0 + lane;
        float acc = 0.f;
#pragma unroll 4
        for (int k = sct * 64; k < sct * 64 + 64; k++)
            acc = fmaf(ws[k], W[(long long)k * N + n], acc);
        red[sct][lane] = acc;
        __syncthreads();
        if (sct == 0) {
            float a = red[0][lane];
#pragma unroll
            for (int j = 1; j < 8; j++) a += red[j][lane];
            out[(long long)b * ldout + n] = a + bias[n];
        }
    } else {
        const int i = (blk - 576) * 256 + threadIdx.x;
        if (i < 768)       bil[i] = g1_b[(i >> 1) + (i & 1) * (H1h/2)];
        else if (i < 1536) { const int j = i - 768;  bil[i] = g2_b[(j >> 1) + (j & 1) * (H1h/2)]; }
        else if (i < 4608) { const int j = i - 1536; bil[i] = gs_b[(j >> 1) + (j & 1) * (CDd/2)]; }
        else if (i < 5376) { const int j = i - 4608; bil[i] = r1_b[(j >> 1) + (j & 1) * (Cc/2)]; }
    }
}

// ================= streams/events =================
struct StreamPack {
    cudaStream_t s1, s2;
    cudaEvent_t eF, eLN, ePrep, eW0, eWall, eA12, eXT, eH2;
    StreamPack() {
        cudaStreamCreateWithFlags(&s1, cudaStreamNonBlocking);
        cudaStreamCreateWithFlags(&s2, cudaStreamNonBlocking);
        cudaEventCreateWithFlags(&eF,    cudaEventDisableTiming);
        cudaEventCreateWithFlags(&eLN,   cudaEventDisableTiming);
        cudaEventCreateWithFlags(&ePrep, cudaEventDisableTiming);
        cudaEventCreateWithFlags(&eW0,   cudaEventDisableTiming);
        cudaEventCreateWithFlags(&eWall, cudaEventDisableTiming);
        cudaEventCreateWithFlags(&eA12,  cudaEventDisableTiming);
        cudaEventCreateWithFlags(&eXT,   cudaEventDisableTiming);
        cudaEventCreateWithFlags(&eH2,   cudaEventDisableTiming);
    }
};
static StreamPack g_sp;

// ================= launch =================
static inline void* symaddr(const void* s) { void* p = nullptr; cudaGetSymbolAddress(&p, s); return p; }

extern "C" void kernel_launch(void* const* d_in, const int* in_sizes, int n_in,
                              void* d_out, int out_size)
{
    const float* x     = (const float*)d_in[0];
    const float* w     = (const float*)d_in[1];
    const float* ln1_g = (const float*)d_in[2];
    const float* ln1_b = (const float*)d_in[3];
    const float* ln2_g = (const float*)d_in[4];
    const float* ln2_b = (const float*)d_in[5];
    const float* g1_W  = (const float*)d_in[6];
    const float* g1_b  = (const float*)d_in[7];
    const float* s1_W  = (const float*)d_in[8];
    const float* s1_b  = (const float*)d_in[9];
    const float* m1_W  = (const float*)d_in[10];
    const float* m1_b  = (const float*)d_in[11];
    const float* g2_W  = (const float*)d_in[12];
    const float* g2_b  = (const float*)d_in[13];
    const float* s2_W  = (const float*)d_in[14];
    const float* s2_b  = (const float*)d_in[15];
    const float* m2_W  = (const float*)d_in[16];
    const float* m2_b  = (const float*)d_in[17];
    const float* gs_W  = (const float*)d_in[18];
    const float* gs_b  = (const float*)d_in[19];
    const float* ss_W  = (const float*)d_in[20];
    const float* ss_b  = (const float*)d_in[21];
    const float* ms_W  = (const float*)d_in[22];
    const float* ms_b  = (const float*)d_in[23];
    const float* r1_W  = (const float*)d_in[24];
    const float* r1_b  = (const float*)d_in[25];
    const float* r2_W  = (const float*)d_in[26];
    const float* r2_b  = (const float*)d_in[27];
    float* out = (float*)d_out;

    float* x2   = (float*)symaddr(g_x2);
    float* h1   = (float*)symaddr(g_h1);
    float* mix  = (float*)symaddr(g_mix);
    float* s12  = (float*)symaddr(g_s12);
    float* ssv  = (float*)symaddr(g_ss);
    float* zb   = (float*)symaddr(g_zero);
    float* bil  = (float*)symaddr(g_bil);
    float* xtf  = (float*)symaddr(g_xtf);
    float* astf = (float*)symaddr(g_astf);
    float* wgs  = (float*)symaddr(g_wgs);
    float* wms  = (float*)symaddr(g_wms);
    __half* xh   = (__half*)symaddr(g_xh);
    __half* xl   = (__half*)symaddr(g_xl);
    __half* a12h = (__half*)symaddr(g_a12h);
    __half* a12l = (__half*)symaddr(g_a12l);
    __half* h2h  = (__half*)symaddr(g_h2h);
    __half* h2l  = (__half*)symaddr(g_h2l);
    __half* h1th = (__half*)symaddr(g_h1th);
    __half* h1tl = (__half*)symaddr(g_h1tl);
    __half* xTh  = (__half*)symaddr(g_xTh);
    __half* xTl  = (__half*)symaddr(g_xTl);
    __half* mTh  = (__half*)symaddr(g_mTh);
    __half* mTl  = (__half*)symaddr(g_mTl);
    __half* wTh  = (__half*)symaddr(g_wTh);
    __half* wTl  = (__half*)symaddr(g_wTl);
    __half* x3h  = (__half*)symaddr(g_x3h);
    __half* x3l  = (__half*)symaddr(g_x3l);

    cudaFuncSetAttribute(gemm_sp<0>, cudaFuncAttributeMaxDynamicSharedMemorySize, GSMEM_SZ);
    cudaFuncSetAttribute(gemm_sp<1>, cudaFuncAttributeMaxDynamicSharedMemorySize, GSMEM_SZ);
    cudaFuncSetAttribute(gemm_sp<2>, cudaFuncAttributeMaxDynamicSharedMemorySize, GSMEM_SZ);
    cudaFuncSetAttribute(gemm_tf<0>, cudaFuncAttributeMaxDynamicSharedMemorySize, TFSMEM_SZ);
    cudaFuncSetAttribute(gemm_tf<2>, cudaFuncAttributeMaxDynamicSharedMemorySize, TFSMEM_SZ);

    const dim3 tb(32, 8);
    cudaStream_t d = 0, s1 = g_sp.s1, s2 = g_sp.s2;

    // ---- fork ----
    cudaEventRecord(g_sp.eF, d);
    cudaStreamWaitEvent(s1, g_sp.eF, 0);
    cudaStreamWaitEvent(s2, g_sp.eF, 0);

    // d: LN1
    ln_split<<<MTOK, 256, 0, d>>>(x, ln1_g, ln1_b, xh, xl);
    cudaEventRecord(g_sp.eLN, d);

    // s1: prep, then xT transpose
    prep_small<<<597, 256, 0, s1>>>(w, s1_W, s1_b, s2_W, s2_b, ss_W, ss_b,
                                    g1_b, g2_b, gs_b, r1_b, s12, ssv, bil);
    cudaEventRecord(g_sp.ePrep, s1);
    cudaStreamWaitEvent(s1, g_sp.eLN, 0);
    transpose_hf2<<<dim3(Cc/32, Tt/32, Bb), tb, 0, s1>>>(xh, xl, xTh, xTl, Tt, Cc,
        (long long)Tt*Cc, (long long)Tt*Cc);
    cudaEventRecord(g_sp.eXT, s1);

    // s2: all weight transposes
    transpose_split_il2<<<dim3(H1h/32, Cc/32, 2), tb, 0, s2>>>(g1_W, g2_W, wTh + W0_OFF, wTl + W0_OFF);
    cudaEventRecord(g_sp.eW0, s2);
    transpose_split   <<<dim3(TDd/32, TDd/32, 1), tb, 0, s2>>>(m1_W, wTh + W1_OFF, wTl + W1_OFF, TDd, TDd, 0, 0);
    transpose_split   <<<dim3(TDd/32, TDd/32, 1), tb, 0, s2>>>(m2_W, wTh + W2_OFF, wTl + W2_OFF, TDd, TDd, 0, 0);
    transpose_tf_il   <<<dim3(CDd/32, Cc/32),     tb, 0, s2>>>(gs_W, wgs, Cc, CDd, CDd/2);
    transpose_tf      <<<dim3(Cc/32, (CDd/2)/32, 1), tb, 0, s2>>>(ms_W, wms, CDd/2, Cc);
    transpose_split_il<<<dim3(Cc/32, Cc/32),      tb, 0, s2>>>(r1_W, wTh + W5_OFF, wTl + W5_OFF, Cc, Cc, Cc/2);
    transpose_split   <<<dim3(Cc/32, (Cc/2)/32, 1), tb, 0, s2>>>(r2_W, wTh + W6_OFF, wTl + W6_OFF, Cc/2, Cc, 0, 0);
    cudaEventRecord(g_sp.eWall, s2);

    // d: big fused GLU GEMM
    cudaStreamWaitEvent(d, g_sp.ePrep, 0);
    cudaStreamWaitEvent(d, g_sp.eW0, 0);
    gemm_sp<2><<<dim3(2*H1h/128, MTOK/128, 1), 256, GSMEM_SZ, d>>>(
        xh, xl, wTh + W0_OFF, wTl + W0_OFF, nullptr, a12h, a12l, bil,
        nullptr, nullptr, nullptr, s12, H1h, MTOK, 2*H1h, Cc, Cc, 0, 0, 0, 0);
    cudaEventRecord(g_sp.eA12, d);
    cudaStreamWaitEvent(d, g_sp.eWall, 0);

    // s1: m2 GEMM (overlapped)
    cudaStreamWaitEvent(s1, g_sp.eA12, 0);
    cudaStreamWaitEvent(s1, g_sp.eWall, 0);
    gemm_sp<0><<<dim3(TDd/128, MTOK/128, 1), 256, GSMEM_SZ, s1>>>(
        a12h + TDd, a12l + TDd, wTh + W2_OFF, wTl + W2_OFF, nullptr, h2h, h2l, m2_b,
        nullptr, nullptr, nullptr, nullptr, 0, MTOK, TDd, TDd, H1h, 0, 0, 0, 0);
    cudaEventRecord(g_sp.eH2, s1);

    // d: m1 -> h1t -> mix -> mT
    gemm_sp<0><<<dim3(TDd/128, MTOK/128, 1), 256, GSMEM_SZ, d>>>(
        a12h, a12l, wTh + W1_OFF, wTl + W1_OFF, h1, nullptr, nullptr, m1_b,
        nullptr, nullptr, nullptr, nullptr, 0, MTOK, TDd, TDd, H1h, 0, 0, 0, 0);
    transpose_split<<<dim3(TDd/32, Tt/32, Bb), tb, 0, d>>>(h1, h1th, h1tl, Tt, TDd,
        (long long)Tt*TDd, (long long)Tt*TDd);
    cudaStreamWaitEvent(d, g_sp.eXT, 0);
    gemm_sp<1><<<dim3(Cc/128, TDd/128, Bb), 256, GSMEM_SZ, d>>>(
        h1th, h1tl, xTh, xTl, mix, nullptr, nullptr, zb,
        nullptr, nullptr, nullptr, nullptr, 0,
        TDd, Cc, Tt, Tt, (long long)TDd*Tt, (long long)Cc*Tt, (long long)TDd*Cc, 0);
    transpose_split<<<dim3(Cc/32, TDd/32, Bb), tb, 0, d>>>(mix, mTh, mTl, TDd, Cc,
        (long long)TDd*Cc, (long long)TDd*Cc);

    // d: x2 = xln + h2 @ mix (join s1)
    cudaStreamWaitEvent(d, g_sp.eH2, 0);
    gemm_sp<0><<<dim3(Cc/128, Tt/128, Bb), 256, GSMEM_SZ, d>>>(
        h2h, h2l, mTh, mTl, x2, nullptr, nullptr, zb, nullptr, xh, xl, nullptr, 0,
        Tt, Cc, TDd, TDd, (long long)Tt*TDd, (long long)Cc*TDd, (long long)Tt*Cc, (long long)Tt*Cc);

    // d: LN2 (tf32) -> gs (tf32) -> ms (tf32) -> head (fp16x3)
    ln_tf<<<MTOK, 256, 0, d>>>(x2, ln2_g, ln2_b, xtf);
    gemm_tf<2><<<dim3(CDd/128, MTOK/128, 1), 256, TFSMEM_SZ, d>>>(
        xtf, wgs, nullptr, astf, nullptr, nullptr, bil + 1536, nullptr,
        ssv, CDd/2, MTOK, CDd, Cc, Cc);
    gemm_tf<0><<<dim3(Cc/128, MTOK/128, 1), 256, TFSMEM_SZ, d>>>(
        astf, wms, x2, nullptr, x3h, x3l, ms_b, x2,
        nullptr, 0, MTOK, Cc, CDd/2, CDd/2);
    gemm_sp<2><<<dim3(Cc/128, MTOK/128, 1), 256, GSMEM_SZ, d>>>(
        x3h, x3l, wTh + W5_OFF, wTl + W5_OFF, nullptr, a12h, a12l, bil + 4608,
        nullptr, nullptr, nullptr, nullptr, 0, MTOK, Cc, Cc, Cc, 0, 0, 0, 0);
    gemm_sp<0><<<dim3(Cc/128, MTOK/128, 1), 256, GSMEM_SZ, d>>>(
        a12h, a12l, wTh + W6_OFF, wTl + W6_OFF, out, nullptr, nullptr, r2_b,
        nullptr, nullptr, nullptr, nullptr, 0, MTOK, Cc, Cc/2, Cc/2, 0, 0, 0, 0);
}

// round 17
// speedup vs baseline: 1.3283x; 1.0936x over previous
#include <cuda_runtime.h>
#include <cuda_fp16.h>
#include <cstdint>
#include <math.h>

// ---------------- problem constants ----------------
#define Bb   8
#define Tt   2048
#define Cc   768
#define WDd  512
#define TDd  384
#define CDd  3072
#define H1h  768
#define MTOK (Bb * Tt)          // 16384

// ---------------- fp32 scratch ----------------
__device__ float g_x2 [MTOK * Cc];
__device__ float g_h1 [MTOK * TDd];
__device__ float g_mix[Bb * TDd * Cc];
__device__ float g_s12[Bb * H1h];
__device__ float g_ss [Bb * (CDd/2)];
__device__ float g_zero[CDd];
__device__ float g_bil[6144];
__device__ float g_xtf [MTOK * Cc];         // LN2 out, tf32-rounded
__device__ float g_astf[MTOK * (CDd/2)];    // gs GLU out, tf32-rounded
__device__ float g_x3tf[MTOK * Cc];         // x3, tf32-rounded
__device__ float g_artf[MTOK * (Cc/2)];     // r1 GLU out, tf32-rounded
__device__ float g_wgs [CDd * Cc];          // gs_W T+il, tf32
__device__ float g_wms [Cc * (CDd/2)];      // ms_W T, tf32
__device__ float g_wr1 [Cc * Cc];           // r1_W T+il, tf32
__device__ float g_wr2 [Cc * (Cc/2)];       // r2_W T, tf32

// ---------------- fp16 split operand buffers (early chain) ----------------
__device__ __half g_xh [MTOK*Cc],        g_xl [MTOK*Cc];
__device__ __half g_a12h[MTOK*H1h],      g_a12l[MTOK*H1h];
__device__ __half g_h2h[MTOK*TDd],       g_h2l[MTOK*TDd];
__device__ __half g_h1th[Bb*TDd*Tt],     g_h1tl[Bb*TDd*Tt];
__device__ __half g_xTh[Bb*Cc*Tt],       g_xTl[Bb*Cc*Tt];
__device__ __half g_mTh[Bb*Cc*TDd],      g_mTl[Bb*Cc*TDd];

// fp16 transposed-weight slices: W0 g1|g2 il, W1 m1, W2 m2
#define W0_OFF 0
#define W1_OFF (W0_OFF + 2*H1h*Cc)
#define W2_OFF (W1_OFF + TDd*TDd)
#define W_TOT  (W2_OFF + TDd*TDd)
__device__ __half g_wTh[W_TOT], g_wTl[W_TOT];

// ---------------- helpers ----------------
__device__ __forceinline__ uint32_t smem_u32(const void* p) {
    uint32_t a;
    asm("{ .reg .u64 t; cvta.to.shared.u64 t, %1; cvt.u32.u64 %0, t; }" : "=r"(a) : "l"(p));
    return a;
}
__device__ __forceinline__ void cpa16(uint32_t s, const void* g) {
    asm volatile("cp.async.cg.shared.global [%0], [%1], 16;" :: "r"(s), "l"(g));
}
__device__ __forceinline__ void ldsm4(uint32_t& r0, uint32_t& r1, uint32_t& r2, uint32_t& r3,
                                      uint32_t a) {
    asm volatile("ldmatrix.sync.aligned.m8n8.x4.shared.b16 {%0,%1,%2,%3}, [%4];"
                 : "=r"(r0), "=r"(r1), "=r"(r2), "=r"(r3) : "r"(a));
}
__device__ __forceinline__ void mma_f16(float* c, const uint32_t* a,
                                        uint32_t b0, uint32_t b1) {
    asm volatile(
        "mma.sync.aligned.m16n8k16.row.col.f32.f16.f16.f32 "
        "{%0,%1,%2,%3}, {%4,%5,%6,%7}, {%8,%9}, {%0,%1,%2,%3};"
        : "+f"(c[0]), "+f"(c[1]), "+f"(c[2]), "+f"(c[3])
        : "r"(a[0]), "r"(a[1]), "r"(a[2]), "r"(a[3]), "r"(b0), "r"(b1));
}
__device__ __forceinline__ void mma_tf32(float* c, const uint32_t* a,
                                         uint32_t b0, uint32_t b1) {
    asm volatile(
        "mma.sync.aligned.m16n8k8.row.col.f32.tf32.tf32.f32 "
        "{%0,%1,%2,%3}, {%4,%5,%6,%7}, {%8,%9}, {%0,%1,%2,%3};"
        : "+f"(c[0]), "+f"(c[1]), "+f"(c[2]), "+f"(c[3])
        : "r"(a[0]), "r"(a[1]), "r"(a[2]), "r"(a[3]), "r"(b0), "r"(b1));
}
__device__ __forceinline__ void split_one(float v, __half& h, __half& l) {
    h = __float2half_rn(v);
    l = __float2half_rn(v - __half2float(h));
}
__device__ __forceinline__ float f2tf(float f) {
    uint32_t u;
    asm("cvt.rna.tf32.f32 %0, %1;" : "=r"(u) : "f"(f));
    return __uint_as_float(u);
}

// ================= split-fp16 GEMM: BK=32, 2-stage (R14 shape, proven) ===========
// ACT: 0=bias(+res), 1=gelu, 2=GLU-pairs (interleaved weights; out N/2 cols)
#define LDBB 80
#define TILE_B (128 * LDBB)
#define GSMEM_SZ (8 * TILE_B)

template <int ACT>
__global__ void __launch_bounds__(256, 2) gemm_sp(
    const __half* __restrict__ Ah_, const __half* __restrict__ Al_,
    const __half* __restrict__ Bh_, const __half* __restrict__ Bl_,
    float* __restrict__ Cf, __half* __restrict__ Ch, __half* __restrict__ Cl,
    const float* __restrict__ bias, const float* __restrict__ resF,
    const __half* __restrict__ resH, const __half* __restrict__ resL,
    const float* __restrict__ scale, int sN,
    int M, int N, int K, int lda,
    long long sA, long long sB, long long sC, long long sR)
{
    extern __shared__ char smem[];
    const uint32_t sbase = smem_u32(smem);
    const int tid = threadIdx.x, wid = tid >> 5, lane = tid & 31;
    const int g = lane >> 2, tg = lane & 3;
    const int wm = (wid >> 1) * 32;
    const int wn = (wid & 1) * 64;

    const int bz = blockIdx.z;
    const long long ldaB = (long long)lda * 2;
    const long long ldbB = (long long)K * 2;

    const int row0 = blockIdx.y * 128;
    const int col0 = blockIdx.x * 128;

    const char* Agh = (const char*)(Ah_ + bz * sA) + (long long)row0 * ldaB;
    const char* Agl = (const char*)(Al_ + bz * sA) + (long long)row0 * ldaB;
    const char* Bgh = (const char*)(Bh_ + bz * sB) + (long long)col0 * ldbB;
    const char* Bgl = (const char*)(Bl_ + bz * sB) + (long long)col0 * ldbB;
    if (Cf) Cf += bz * sC;
    if (Ch) { Ch += bz * sC; Cl += bz * sC; }
    if (resF) resF += bz * sR;
    if (resH) { resH += bz * sR; resL += bz * sR; }

    const int nIter = K >> 5;
    const int rr = tid >> 2;
    const int cbo = (tid & 3) * 16;

    auto issue = [&](int i) {
        const uint32_t sb0 = sbase + (uint32_t)(i & 1) * 4 * TILE_B;
        const long long ko = (long long)i * 64;
#pragma unroll
        for (int t = 0; t < 2; t++) {
            const int r = rr + t * 64;
            const uint32_t so = (uint32_t)r * LDBB + cbo;
            cpa16(sb0 + so,              Agh + (long long)r * ldaB + ko + cbo);
            cpa16(sb0 + TILE_B + so,     Agl + (long long)r * ldaB + ko + cbo);
            cpa16(sb0 + 2 * TILE_B + so, Bgh + (long long)r * ldbB + ko + cbo);
            cpa16(sb0 + 3 * TILE_B + so, Bgl + (long long)r * ldbB + ko + cbo);
        }
    };

    issue(0); asm volatile("cp.async.commit_group;");
    issue(1); asm volatile("cp.async.commit_group;");

    const uint32_t aOff0 = (uint32_t)(wm + (lane & 7) + ((lane >> 3) & 1) * 8) * LDBB
                         + (uint32_t)(lane >> 4) * 16;
    const uint32_t aOff1 = aOff0 + 16 * LDBB;
    const uint32_t bOff0 = (uint32_t)(wn + (lane & 7) + (lane >> 4) * 8) * LDBB
                         + (uint32_t)((lane >> 3) & 1) * 16;

    float acc[2][8][4];
#pragma unroll
    for (int mt = 0; mt < 2; mt++)
#pragma unroll
        for (int nt = 0; nt < 8; nt++)
#pragma unroll
            for (int q = 0; q < 4; q++) acc[mt][nt][q] = 0.f;

    for (int i = 0; i < nIter; i++) {
        asm volatile("cp.async.wait_group 1;");
        __syncthreads();
        const uint32_t st = sbase + (uint32_t)(i & 1) * 4 * TILE_B;
#pragma unroll
        for (int kk = 0; kk < 2; kk++) {
            const uint32_t kb = kk * 32;
            uint32_t ah[2][4], al[2][4];
            ldsm4(ah[0][0], ah[0][1], ah[0][2], ah[0][3], st + aOff0 + kb);
            ldsm4(ah[1][0], ah[1][1], ah[1][2], ah[1][3], st + aOff1 + kb);
            ldsm4(al[0][0], al[0][1], al[0][2], al[0][3], st + TILE_B + aOff0 + kb);
            ldsm4(al[1][0], al[1][1], al[1][2], al[1][3], st + TILE_B + aOff1 + kb);
            {
                uint32_t bh[4][4];
#pragma unroll
                for (int ntp = 0; ntp < 4; ntp++)
                    ldsm4(bh[ntp][0], bh[ntp][1], bh[ntp][2], bh[ntp][3],
                          st + 2 * TILE_B + bOff0 + (uint32_t)ntp * 16 * LDBB + kb);
#pragma unroll
                for (int ntp = 0; ntp < 4; ntp++) {
                    const int n0 = 2 * ntp, n1 = 2 * ntp + 1;
                    mma_f16(acc[0][n0], ah[0], bh[ntp][0], bh[ntp][1]);
                    mma_f16(acc[1][n0], ah[1], bh[ntp][0], bh[ntp][1]);
                    mma_f16(acc[0][n1], ah[0], bh[ntp][2], bh[ntp][3]);
                    mma_f16(acc[1][n1], ah[1], bh[ntp][2], bh[ntp][3]);
                }
#pragma unroll
                for (int ntp = 0; ntp < 4; ntp++) {
                    const int n0 = 2 * ntp, n1 = 2 * ntp + 1;
                    mma_f16(acc[0][n0], al[0], bh[ntp][0], bh[ntp][1]);
                    mma_f16(acc[1][n0], al[1], bh[ntp][0], bh[ntp][1]);
                    mma_f16(acc[0][n1], al[0], bh[ntp][2], bh[ntp][3]);
                    mma_f16(acc[1][n1], al[1], bh[ntp][2], bh[ntp][3]);
                }
            }
            {
                uint32_t bl[4][4];
#pragma unroll
                for (int ntp = 0; ntp < 4; ntp++)
                    ldsm4(bl[ntp][0], bl[ntp][1], bl[ntp][2], bl[ntp][3],
                          st + 3 * TILE_B + bOff0 + (uint32_t)ntp * 16 * LDBB + kb);
#pragma unroll
                for (int ntp = 0; ntp < 4; ntp++) {
                    const int n0 = 2 * ntp, n1 = 2 * ntp + 1;
                    mma_f16(acc[0][n0], ah[0], bl[ntp][0], bl[ntp][1]);
                    mma_f16(acc[1][n0], ah[1], bl[ntp][0], bl[ntp][1]);
                    mma_f16(acc[0][n1], ah[0], bl[ntp][2], bl[ntp][3]);
                    mma_f16(acc[1][n1], ah[1], bl[ntp][2], bl[ntp][3]);
                }
            }
        }
        __syncthreads();
        if (i + 2 < nIter) issue(i + 2);
        asm volatile("cp.async.commit_group;");
    }
    asm volatile("cp.async.wait_all;");

    const int Nout = (ACT == 2) ? (N >> 1) : N;
#pragma unroll
    for (int mt = 0; mt < 2; mt++) {
        const int r = row0 + wm + mt * 16 + g;
#pragma unroll
        for (int nt = 0; nt < 8; nt++) {
            const int c = col0 + wn + nt * 8 + tg * 2;
            const float bx = __ldg(&bias[c]), by = __ldg(&bias[c + 1]);
            float v0 = acc[mt][nt][0] + bx;
            float v1 = acc[mt][nt][1] + by;
            float v2 = acc[mt][nt][2] + bx;
            float v3 = acc[mt][nt][3] + by;
            if (ACT == 2) {
                const int c2 = c >> 1;
                float o0 = v0 / (1.0f + __expf(-v1));
                float o1 = v2 / (1.0f + __expf(-v3));
                if (scale) {
                    o0 *= __ldg(&scale[(r / Tt) * sN + c2]);
                    o1 *= __ldg(&scale[((r + 8) / Tt) * sN + c2]);
                }
                __half h0, l0, h1, l1;
                split_one(o0, h0, l0); split_one(o1, h1, l1);
                Ch[(long long)r * Nout + c2] = h0;
                Cl[(long long)r * Nout + c2] = l0;
                Ch[(long long)(r + 8) * Nout + c2] = h1;
                Cl[(long long)(r + 8) * Nout + c2] = l1;
            } else {
                if (resF) {
                    const float2 r0 = *(const float2*)(resF + (long long)r * N + c);
                    const float2 r1 = *(const float2*)(resF + (long long)(r + 8) * N + c);
                    v0 += r0.x; v1 += r0.y; v2 += r1.x; v3 += r1.y;
                }
                if (resH) {
                    const __half2 h0 = *(const __half2*)(resH + (long long)r * N + c);
                    const __half2 l0 = *(const __half2*)(resL + (long long)r * N + c);
                    const __half2 h1 = *(const __half2*)(resH + (long long)(r + 8) * N + c);
                    const __half2 l1 = *(const __half2*)(resL + (long long)(r + 8) * N + c);
                    v0 += __half2float(h0.x) + __half2float(l0.x);
                    v1 += __half2float(h0.y) + __half2float(l0.y);
                    v2 += __half2float(h1.x) + __half2float(l1.x);
                    v3 += __half2float(h1.y) + __half2float(l1.y);
                }
                if (ACT == 1) {
                    v0 = 0.5f * v0 * (1.0f + erff(v0 * 0.70710678118654752f));
                    v1 = 0.5f * v1 * (1.0f + erff(v1 * 0.70710678118654752f));
                    v2 = 0.5f * v2 * (1.0f + erff(v2 * 0.70710678118654752f));
                    v3 = 0.5f * v3 * (1.0f + erff(v3 * 0.70710678118654752f));
                }
                if (Cf) {
                    *(float2*)(Cf + (long long)r * N + c)       = make_float2(v0, v1);
                    *(float2*)(Cf + (long long)(r + 8) * N + c) = make_float2(v2, v3);
                }
                if (Ch) {
                    __half2 h01, l01, h23, l23;
                    split_one(v0, h01.x, l01.x); split_one(v1, h01.y, l01.y);
                    split_one(v2, h23.x, l23.x); split_one(v3, h23.y, l23.y);
                    *(__half2*)(Ch + (long long)r * N + c)       = h01;
                    *(__half2*)(Cl + (long long)r * N + c)       = l01;
                    *(__half2*)(Ch + (long long)(r + 8) * N + c) = h23;
                    *(__half2*)(Cl + (long long)(r + 8) * N + c) = l23;
                }
            }
        }
    }
}

// ================= single-pass tf32 GEMM: BK=32, 2-stage cp.async ================
// ACT2: GLU pairs -> Ctf (tf32, [M][N/2], *scale). ACT0: bias(+resF) -> Cf / Ctf.
#define TFW 36
#define TFTILE_B (128 * TFW * 4)
#define TFSMEM_SZ (4 * TFTILE_B)

template <int ACT>
__global__ void __launch_bounds__(256, 2) gemm_tf(
    const float* __restrict__ A_, const float* __restrict__ B_,
    float* __restrict__ Cf, float* __restrict__ Ctf,
    __half* __restrict__ Ch, __half* __restrict__ Cl,
    const float* __restrict__ bias, const float* __restrict__ resF,
    const float* __restrict__ scale, int sN,
    int M, int N, int K, int lda)
{
    extern __shared__ char smem[];
    const uint32_t sbase = smem_u32(smem);
    const int tid = threadIdx.x, wid = tid >> 5, lane = tid & 31;
    const int g = lane >> 2, tg = lane & 3;
    const int wm = (wid >> 1) * 32;
    const int wn = (wid & 1) * 64;

    const long long ldaB = (long long)lda * 4;
    const long long ldbB = (long long)K * 4;

    const int row0 = blockIdx.y * 128;
    const int col0 = blockIdx.x * 128;
    const char* Ag = (const char*)A_ + (long long)row0 * ldaB;
    const char* Bg = (const char*)B_ + (long long)col0 * ldbB;

    const int nIter = K >> 5;

    auto issue = [&](int i) {
        const uint32_t sb0 = sbase + (uint32_t)(i & 1) * 2 * TFTILE_B;
        const long long ko = (long long)i * 128;
#pragma unroll
        for (int q = 0; q < 4; q++) {
            const int ch = tid + q * 256;
            const int r = ch >> 3;
            const uint32_t cb = (uint32_t)(ch & 7) * 16;
            const uint32_t so = (uint32_t)r * (TFW * 4) + cb;
            cpa16(sb0 + so,            Ag + (long long)r * ldaB + ko + cb);
            cpa16(sb0 + TFTILE_B + so, Bg + (long long)r * ldbB + ko + cb);
        }
    };

    issue(0); asm volatile("cp.async.commit_group;");
    issue(1); asm volatile("cp.async.commit_group;");

    float acc[2][8][4];
#pragma unroll
    for (int mt = 0; mt < 2; mt++)
#pragma unroll
        for (int nt = 0; nt < 8; nt++)
#pragma unroll
            for (int q = 0; q < 4; q++) acc[mt][nt][q] = 0.f;

    for (int i = 0; i < nIter; i++) {
        asm volatile("cp.async.wait_group 1;");
        __syncthreads();
        const float* As = (const float*)(smem + (size_t)(i & 1) * 2 * TFTILE_B);
        const float* Bs = As + TFW * 128;
#pragma unroll
        for (int kk = 0; kk < 4; kk++) {
            const int k0 = kk * 8;
            uint32_t af[2][4];
#pragma unroll
            for (int mt = 0; mt < 2; mt++) {
                const int rm = wm + mt * 16;
                af[mt][0] = __float_as_uint(As[(rm + g) * TFW + k0 + tg]);
                af[mt][1] = __float_as_uint(As[(rm + 8 + g) * TFW + k0 + tg]);
                af[mt][2] = __float_as_uint(As[(rm + g) * TFW + k0 + tg + 4]);
                af[mt][3] = __float_as_uint(As[(rm + 8 + g) * TFW + k0 + tg + 4]);
            }
#pragma unroll
            for (int nt = 0; nt < 8; nt++) {
                const int cn = wn + nt * 8;
                const uint32_t b0 = __float_as_uint(Bs[(cn + g) * TFW + k0 + tg]);
                const uint32_t b1 = __float_as_uint(Bs[(cn + g) * TFW + k0 + tg + 4]);
                mma_tf32(acc[0][nt], af[0], b0, b1);
                mma_tf32(acc[1][nt], af[1], b0, b1);
            }
        }
        __syncthreads();
        if (i + 2 < nIter) issue(i + 2);
        asm volatile("cp.async.commit_group;");
    }
    asm volatile("cp.async.wait_all;");

    const int Nout = (ACT == 2) ? (N >> 1) : N;
#pragma unroll
    for (int mt = 0; mt < 2; mt++) {
        const int r = row0 + wm + mt * 16 + g;
#pragma unroll
        for (int nt = 0; nt < 8; nt++) {
            const int c = col0 + wn + nt * 8 + tg * 2;
            const float bx = __ldg(&bias[c]), by = __ldg(&bias[c + 1]);
            float v0 = acc[mt][nt][0] + bx;
            float v1 = acc[mt][nt][1] + by;
            float v2 = acc[mt][nt][2] + bx;
            float v3 = acc[mt][nt][3] + by;
            if (ACT == 2) {
                const int c2 = c >> 1;
                float o0 = v0 / (1.0f + __expf(-v1));
                float o1 = v2 / (1.0f + __expf(-v3));
                if (scale) {
                    o0 *= __ldg(&scale[(r / Tt) * sN + c2]);
                    o1 *= __ldg(&scale[((r + 8) / Tt) * sN + c2]);
                }
                Ctf[(long long)r * Nout + c2]       = f2tf(o0);
                Ctf[(long long)(r + 8) * Nout + c2] = f2tf(o1);
            } else {
                if (resF) {
                    const float2 r0 = *(const float2*)(resF + (long long)r * N + c);
                    const float2 r1 = *(const float2*)(resF + (long long)(r + 8) * N + c);
                    v0 += r0.x; v1 += r0.y; v2 += r1.x; v3 += r1.y;
                }
                if (Cf) {
                    *(float2*)(Cf + (long long)r * N + c)       = make_float2(v0, v1);
                    *(float2*)(Cf + (long long)(r + 8) * N + c) = make_float2(v2, v3);
                }
                if (Ctf) {
                    Ctf[(long long)r * N + c]           = f2tf(v0);
                    Ctf[(long long)r * N + c + 1]       = f2tf(v1);
                    Ctf[(long long)(r + 8) * N + c]     = f2tf(v2);
                    Ctf[(long long)(r + 8) * N + c + 1] = f2tf(v3);
                }
                if (Ch) {
                    __half2 h01, l01, h23, l23;
                    split_one(v0, h01.x, l01.x); split_one(v1, h01.y, l01.y);
                    split_one(v2, h23.x, l23.x); split_one(v3, h23.y, l23.y);
                    *(__half2*)(Ch + (long long)r * N + c)       = h01;
                    *(__half2*)(Cl + (long long)r * N + c)       = l01;
                    *(__half2*)(Ch + (long long)(r + 8) * N + c) = h23;
                    *(__half2*)(Cl + (long long)(r + 8) * N + c) = l23;
                }
            }
        }
    }
}

// ================= transposes =================
__global__ void transpose_split(const float* __restrict__ in,
                                __half* __restrict__ oh, __half* __restrict__ ol,
                                int R, int Cn, long long sIn, long long sOut)
{
    __shared__ float t[32][33];
    const int bz = blockIdx.z;
    in += bz * sIn; oh += bz * sOut; ol += bz * sOut;
    const int c0 = blockIdx.x * 32, r0 = blockIdx.y * 32;
    const int x = threadIdx.x, y = threadIdx.y;
#pragma unroll
    for (int dy = 0; dy < 32; dy += 8)
        t[y + dy][x] = in[(long long)(r0 + y + dy) * Cn + c0 + x];
    __syncthreads();
#pragma unroll
    for (int dy = 0; dy < 32; dy += 8) {
        __half h, l;
        split_one(t[x][y + dy], h, l);
        const long long o = (long long)(c0 + y + dy) * R + r0 + x;
        oh[o] = h; ol[o] = l;
    }
}

__global__ void transpose_hf2(const __half* __restrict__ ih, const __half* __restrict__ il,
                              __half* __restrict__ oh, __half* __restrict__ ol,
                              int R, int Cn, long long sIn, long long sOut)
{
    __shared__ __half th[32][34];
    __shared__ __half tl[32][34];
    const int bz = blockIdx.z;
    ih += bz * sIn; il += bz * sIn; oh += bz * sOut; ol += bz * sOut;
    const int c0 = blockIdx.x * 32, r0 = blockIdx.y * 32;
    const int x = threadIdx.x, y = threadIdx.y;
#pragma unroll
    for (int dy = 0; dy < 32; dy += 8) {
        const long long o = (long long)(r0 + y + dy) * Cn + c0 + x;
        th[y + dy][x] = ih[o];
        tl[y + dy][x] = il[o];
    }
    __syncthreads();
#pragma unroll
    for (int dy = 0; dy < 32; dy += 8) {
        const long long o = (long long)(c0 + y + dy) * R + r0 + x;
        oh[o] = th[x][y + dy];
        ol[o] = tl[x][y + dy];
    }
}

__global__ void transpose_split_hf(const float* __restrict__ in,
                                   __half* __restrict__ oh, __half* __restrict__ ol,
                                   int R, int Cn, int Hhalf)   // il variant for r-weights unused
{
    // (kept for symmetry; not used)
}

__global__ void transpose_split_il2(const float* __restrict__ g1W,
                                    const float* __restrict__ g2W,
                                    __half* __restrict__ oh, __half* __restrict__ ol)
{
    __shared__ float t[32][33];
    const float* in = blockIdx.z ? g2W : g1W;
    const long long dofs = blockIdx.z ? (long long)H1h * Cc : 0;
    const int c0 = blockIdx.x * 32, r0 = blockIdx.y * 32;
    const int x = threadIdx.x, y = threadIdx.y;
#pragma unroll
    for (int dy = 0; dy < 32; dy += 8)
        t[y + dy][x] = in[(long long)(r0 + y + dy) * H1h + c0 + x];
    __syncthreads();
#pragma unroll
    for (int dy = 0; dy < 32; dy += 8) {
        const int c = c0 + y + dy;
        const int dr = (c < H1h/2) ? 2 * c : 2 * (c - H1h/2) + 1;
        __half h, l;
        split_one(t[x][y + dy], h, l);
        const long long o = dofs + (long long)dr * Cc + r0 + x;
        oh[o] = h; ol[o] = l;
    }
}

// fp16 split transpose (no interleave) for m1/m2 weights
__global__ void transpose_split_w(const float* __restrict__ in,
                                  __half* __restrict__ oh, __half* __restrict__ ol,
                                  int R, int Cn)
{
    __shared__ float t[32][33];
    const int c0 = blockIdx.x * 32, r0 = blockIdx.y * 32;
    const int x = threadIdx.x, y = threadIdx.y;
#pragma unroll
    for (int dy = 0; dy < 32; dy += 8)
        t[y + dy][x] = in[(long long)(r0 + y + dy) * Cn + c0 + x];
    __syncthreads();
#pragma unroll
    for (int dy = 0; dy < 32; dy += 8) {
        __half h, l;
        split_one(t[x][y + dy], h, l);
        const long long o = (long long)(c0 + y + dy) * R + r0 + x;
        oh[o] = h; ol[o] = l;
    }
}

// fp32 -> tf32 fp32 transposes (tail weights)
__global__ void transpose_tf(const float* __restrict__ in, float* __restrict__ o,
                             int R, int Cn)
{
    __shared__ float t[32][33];
    const int c0 = blockIdx.x * 32, r0 = blockIdx.y * 32;
    const int x = threadIdx.x, y = threadIdx.y;
#pragma unroll
    for (int dy = 0; dy < 32; dy += 8)
        t[y + dy][x] = in[(long long)(r0 + y + dy) * Cn + c0 + x];
    __syncthreads();
#pragma unroll
    for (int dy = 0; dy < 32; dy += 8)
        o[(long long)(c0 + y + dy) * R + r0 + x] = f2tf(t[x][y + dy]);
}

__global__ void transpose_tf_il(const float* __restrict__ in, float* __restrict__ o,
                                int R, int Cn, int Hhalf)
{
    __shared__ float t[32][33];
    const int c0 = blockIdx.x * 32, r0 = blockIdx.y * 32;
    const int x = threadIdx.x, y = threadIdx.y;
#pragma unroll
    for (int dy = 0; dy < 32; dy += 8)
        t[y + dy][x] = in[(long long)(r0 + y + dy) * Cn + c0 + x];
    __syncthreads();
#pragma unroll
    for (int dy = 0; dy < 32; dy += 8) {
        const int c = c0 + y + dy;
        const int dr = (c < Hhalf) ? 2 * c : 2 * (c - Hhalf) + 1;
        o[(long long)dr * R + r0 + x] = f2tf(t[x][y + dy]);
    }
}

// ================= LayerNorms =================
__global__ __launch_bounds__(256) void ln_split(const float* __restrict__ x,
                                                const float* __restrict__ g,
                                                const float* __restrict__ b,
                                                __half* __restrict__ oh,
                                                __half* __restrict__ ol)
{
    const int row = blockIdx.x;
    const float* xr = x + (long long)row * Cc;
    const int tid = threadIdx.x;
    float v0 = xr[tid], v1 = xr[tid + 256], v2 = xr[tid + 512];
    float s = v0 + v1 + v2;
    float q = v0 * v0 + v1 * v1 + v2 * v2;
    for (int off = 16; off > 0; off >>= 1) {
        s += __shfl_down_sync(0xffffffff, s, off);
        q += __shfl_down_sync(0xffffffff, q, off);
    }
    __shared__ float ssm[8], sqm[8];
    const int wid = tid >> 5, lid = tid & 31;
    if (lid == 0) { ssm[wid] = s; sqm[wid] = q; }
    __syncthreads();
    if (tid < 8) { s = ssm[tid]; q = sqm[tid]; }
    if (wid == 0) {
        for (int off = 4; off > 0; off >>= 1) {
            s += __shfl_down_sync(0x000000ff, s, off);
            q += __shfl_down_sync(0x000000ff, q, off);
        }
        if (tid == 0) { ssm[0] = s; sqm[0] = q; }
    }
    __syncthreads();
    const float mu  = ssm[0] * (1.0f / Cc);
    const float var = sqm[0] * (1.0f / Cc) - mu * mu;
    const float rs  = rsqrtf(var + 1e-6f);
#pragma unroll
    for (int t = 0; t < 3; t++) {
        const int j = tid + t * 256;
        const float vv = t == 0 ? v0 : (t == 1 ? v1 : v2);
        const float v = (vv - mu) * rs * g[j] + b[j];
        const long long o = (long long)row * Cc + j;
        __half h, l;
        split_one(v, h, l);
        oh[o] = h; ol[o] = l;
    }
}

__global__ __launch_bounds__(256) void ln_tf(const float* __restrict__ x,
                                             const float* __restrict__ g,
                                             const float* __restrict__ b,
                                             float* __restrict__ o)
{
    const int row = blockIdx.x;
    const float* xr = x + (long long)row * Cc;
    const int tid = threadIdx.x;
    float v0 = xr[tid], v1 = xr[tid + 256], v2 = xr[tid + 512];
    float s = v0 + v1 + v2;
    float q = v0 * v0 + v1 * v1 + v2 * v2;
    for (int off = 16; off > 0; off >>= 1) {
        s += __shfl_down_sync(0xffffffff, s, off);
        q += __shfl_down_sync(0xffffffff, q, off);
    }
    __shared__ float ssm[8], sqm[8];
    const int wid = tid >> 5, lid = tid & 31;
    if (lid == 0) { ssm[wid] = s; sqm[wid] = q; }
    __syncthreads();
    if (tid < 8) { s = ssm[tid]; q = sqm[tid]; }
    if (wid == 0) {
        for (int off = 4; off > 0; off >>= 1) {
            s += __shfl_down_sync(0x000000ff, s, off);
            q += __shfl_down_sync(0x000000ff, q, off);
        }
        if (tid == 0) { ssm[0] = s; sqm[0] = q; }
    }
    __syncthreads();
    const float mu  = ssm[0] * (1.0f / Cc);
    const float var = sqm[0] * (1.0f / Cc) - mu * mu;
    const float rs  = rsqrtf(var + 1e-6f);
#pragma unroll
    for (int t = 0; t < 3; t++) {
        const int j = tid + t * 256;
        const float vv = t == 0 ? v0 : (t == 1 ? v1 : v2);
        o[(long long)row * Cc + j] = f2tf((vv - mu) * rs * g[j] + b[j]);
    }
}

// ================= all small prep in ONE launch =================
__global__ __launch_bounds__(256) void prep_small(
    const float* __restrict__ w,
    const float* __restrict__ s1_W, const float* __restrict__ s1_b,
    const float* __restrict__ s2_W, const float* __restrict__ s2_b,
    const float* __restrict__ ss_W, const float* __restrict__ ss_b,
    const float* __restrict__ g1_b, const float* __restrict__ g2_b,
    const float* __restrict__ gs_b, const float* __restrict__ r1_b,
    float* __restrict__ s12, float* __restrict__ ssv, float* __restrict__ bil)
{
    const int blk = blockIdx.x;
    if (blk < 576) {
        const float* W; const float* bias; float* out; int N, ldout, b, n0;
        const float* wr;
        if (blk < 96)       { const int i = blk;       b = i / 12; n0 = (i % 12) * 32; W = s1_W; bias = s1_b; out = s12;           N = TDd;   ldout = H1h;   wr = w + (long long)b * 2 * WDd; }
        else if (blk < 192) { const int i = blk - 96;  b = i / 12; n0 = (i % 12) * 32; W = s2_W; bias = s2_b; out = s12 + TDd;     N = TDd;   ldout = H1h;   wr = w + (long long)b * 2 * WDd; }
        else                { const int i = blk - 192; b = i / 48; n0 = (i % 48) * 32; W = ss_W; bias = ss_b; out = ssv;           N = CDd/2; ldout = CDd/2; wr = w + (long long)b * 2 * WDd + WDd; }
        __shared__ float ws[WDd];
        __shared__ float red[8][32];
        for (int k = threadIdx.x; k < WDd; k += 256) ws[k] = wr[k];
        __syncthreads();
        const int lane = threadIdx.x & 31, sct = threadIdx.x >> 5;
        const int n = n0 + lane;
        float acc = 0.f;
#pragma unroll 4
        for (int k = sct * 64; k < sct * 64 + 64; k++)
            acc = fmaf(ws[k], W[(long long)k * N + n], acc);
        red[sct][lane] = acc;
        __syncthreads();
        if (sct == 0) {
            float a = red[0][lane];
#pragma unroll
            for (int j = 1; j < 8; j++) a += red[j][lane];
            out[(long long)b * ldout + n] = a + bias[n];
        }
    } else {
        const int i = (blk - 576) * 256 + threadIdx.x;
        if (i < 768)       bil[i] = g1_b[(i >> 1) + (i & 1) * (H1h/2)];
        else if (i < 1536) { const int j = i - 768;  bil[i] = g2_b[(j >> 1) + (j & 1) * (H1h/2)]; }
        else if (i < 4608) { const int j = i - 1536; bil[i] = gs_b[(j >> 1) + (j & 1) * (CDd/2)]; }
        else if (i < 5376) { const int j = i - 4608; bil[i] = r1_b[(j >> 1) + (j & 1) * (Cc/2)]; }
    }
}

// ================= streams/events =================
struct StreamPack {
    cudaStream_t s1, s2;
    cudaEvent_t eF, eLN, ePrep, eW0, eWall, eA12, eXT, eH2;
    StreamPack() {
        cudaStreamCreateWithFlags(&s1, cudaStreamNonBlocking);
        cudaStreamCreateWithFlags(&s2, cudaStreamNonBlocking);
        cudaEventCreateWithFlags(&eF,    cudaEventDisableTiming);
        cudaEventCreateWithFlags(&eLN,   cudaEventDisableTiming);
        cudaEventCreateWithFlags(&ePrep, cudaEventDisableTiming);
        cudaEventCreateWithFlags(&eW0,   cudaEventDisableTiming);
        cudaEventCreateWithFlags(&eWall, cudaEventDisableTiming);
        cudaEventCreateWithFlags(&eA12,  cudaEventDisableTiming);
        cudaEventCreateWithFlags(&eXT,   cudaEventDisableTiming);
        cudaEventCreateWithFlags(&eH2,   cudaEventDisableTiming);
    }
};
static StreamPack g_sp;

// ================= launch =================
static inline void* symaddr(const void* s) { void* p = nullptr; cudaGetSymbolAddress(&p, s); return p; }

extern "C" void kernel_launch(void* const* d_in, const int* in_sizes, int n_in,
                              void* d_out, int out_size)
{
    const float* x     = (const float*)d_in[0];
    const float* w     = (const float*)d_in[1];
    const float* ln1_g = (const float*)d_in[2];
    const float* ln1_b = (const float*)d_in[3];
    const float* ln2_g = (const float*)d_in[4];
    const float* ln2_b = (const float*)d_in[5];
    const float* g1_W  = (const float*)d_in[6];
    const float* g1_b  = (const float*)d_in[7];
    const float* s1_W  = (const float*)d_in[8];
    const float* s1_b  = (const float*)d_in[9];
    const float* m1_W  = (const float*)d_in[10];
    const float* m1_b  = (const float*)d_in[11];
    const float* g2_W  = (const float*)d_in[12];
    const float* g2_b  = (const float*)d_in[13];
    const float* s2_W  = (const float*)d_in[14];
    const float* s2_b  = (const float*)d_in[15];
    const float* m2_W  = (const float*)d_in[16];
    const float* m2_b  = (const float*)d_in[17];
    const float* gs_W  = (const float*)d_in[18];
    const float* gs_b  = (const float*)d_in[19];
    const float* ss_W  = (const float*)d_in[20];
    const float* ss_b  = (const float*)d_in[21];
    const float* ms_W  = (const float*)d_in[22];
    const float* ms_b  = (const float*)d_in[23];
    const float* r1_W  = (const float*)d_in[24];
    const float* r1_b  = (const float*)d_in[25];
    const float* r2_W  = (const float*)d_in[26];
    const float* r2_b  = (const float*)d_in[27];
    float* out = (float*)d_out;

    float* x2   = (float*)symaddr(g_x2);
    float* h1   = (float*)symaddr(g_h1);
    float* mix  = (float*)symaddr(g_mix);
    float* s12  = (float*)symaddr(g_s12);
    float* ssv  = (float*)symaddr(g_ss);
    float* zb   = (float*)symaddr(g_zero);
    float* bil  = (float*)symaddr(g_bil);
    float* xtf  = (float*)symaddr(g_xtf);
    float* astf = (float*)symaddr(g_astf);
    float* x3tf = (float*)symaddr(g_x3tf);
    float* artf = (float*)symaddr(g_artf);
    float* wgs  = (float*)symaddr(g_wgs);
    float* wms  = (float*)symaddr(g_wms);
    float* wr1  = (float*)symaddr(g_wr1);
    float* wr2  = (float*)symaddr(g_wr2);
    __half* xh   = (__half*)symaddr(g_xh);
    __half* xl   = (__half*)symaddr(g_xl);
    __half* a12h = (__half*)symaddr(g_a12h);
    __half* a12l = (__half*)symaddr(g_a12l);
    __half* h2h  = (__half*)symaddr(g_h2h);
    __half* h2l  = (__half*)symaddr(g_h2l);
    __half* h1th = (__half*)symaddr(g_h1th);
    __half* h1tl = (__half*)symaddr(g_h1tl);
    __half* xTh  = (__half*)symaddr(g_xTh);
    __half* xTl  = (__half*)symaddr(g_xTl);
    __half* mTh  = (__half*)symaddr(g_mTh);
    __half* mTl  = (__half*)symaddr(g_mTl);
    __half* wTh  = (__half*)symaddr(g_wTh);
    __half* wTl  = (__half*)symaddr(g_wTl);

    cudaFuncSetAttribute(gemm_sp<0>, cudaFuncAttributeMaxDynamicSharedMemorySize, GSMEM_SZ);
    cudaFuncSetAttribute(gemm_sp<1>, cudaFuncAttributeMaxDynamicSharedMemorySize, GSMEM_SZ);
    cudaFuncSetAttribute(gemm_sp<2>, cudaFuncAttributeMaxDynamicSharedMemorySize, GSMEM_SZ);
    cudaFuncSetAttribute(gemm_tf<0>, cudaFuncAttributeMaxDynamicSharedMemorySize, TFSMEM_SZ);
    cudaFuncSetAttribute(gemm_tf<2>, cudaFuncAttributeMaxDynamicSharedMemorySize, TFSMEM_SZ);

    const dim3 tb(32, 8);
    cudaStream_t d = 0, s1 = g_sp.s1, s2 = g_sp.s2;

    // ---- fork ----
    cudaEventRecord(g_sp.eF, d);
    cudaStreamWaitEvent(s1, g_sp.eF, 0);
    cudaStreamWaitEvent(s2, g_sp.eF, 0);

    // d: LN1 -> fp16 split
    ln_split<<<MTOK, 256, 0, d>>>(x, ln1_g, ln1_b, xh, xl);
    cudaEventRecord(g_sp.eLN, d);

    // s1: prep, then xT transpose
    prep_small<<<597, 256, 0, s1>>>(w, s1_W, s1_b, s2_W, s2_b, ss_W, ss_b,
                                    g1_b, g2_b, gs_b, r1_b, s12, ssv, bil);
    cudaEventRecord(g_sp.ePrep, s1);
    cudaStreamWaitEvent(s1, g_sp.eLN, 0);
    transpose_hf2<<<dim3(Cc/32, Tt/32, Bb), tb, 0, s1>>>(xh, xl, xTh, xTl, Tt, Cc,
        (long long)Tt*Cc, (long long)Tt*Cc);
    cudaEventRecord(g_sp.eXT, s1);

    // s2: weight transposes — fp16 for early chain, tf32 for tail
    transpose_split_il2<<<dim3(H1h/32, Cc/32, 2), tb, 0, s2>>>(g1_W, g2_W, wTh + W0_OFF, wTl + W0_OFF);
    cudaEventRecord(g_sp.eW0, s2);
    transpose_split_w<<<dim3(TDd/32, TDd/32, 1), tb, 0, s2>>>(m1_W, wTh + W1_OFF, wTl + W1_OFF, TDd, TDd);
    transpose_split_w<<<dim3(TDd/32, TDd/32, 1), tb, 0, s2>>>(m2_W, wTh + W2_OFF, wTl + W2_OFF, TDd, TDd);
    transpose_tf_il  <<<dim3(CDd/32, Cc/32),     tb, 0, s2>>>(gs_W, wgs, Cc, CDd, CDd/2);
    transpose_tf     <<<dim3(Cc/32, (CDd/2)/32, 1), tb, 0, s2>>>(ms_W, wms, CDd/2, Cc);
    transpose_tf_il  <<<dim3(Cc/32, Cc/32),      tb, 0, s2>>>(r1_W, wr1, Cc, Cc, Cc/2);
    transpose_tf     <<<dim3(Cc/32, (Cc/2)/32, 1), tb, 0, s2>>>(r2_W, wr2, Cc/2, Cc);
    cudaEventRecord(g_sp.eWall, s2);

    // d: big fused g1|g2 GLU GEMM (fp16x3)
    cudaStreamWaitEvent(d, g_sp.ePrep, 0);
    cudaStreamWaitEvent(d, g_sp.eW0, 0);
    gemm_sp<2><<<dim3(2*H1h/128, MTOK/128, 1), 256, GSMEM_SZ, d>>>(
        xh, xl, wTh + W0_OFF, wTl + W0_OFF, nullptr, a12h, a12l, bil,
        nullptr, nullptr, nullptr, s12, H1h, MTOK, 2*H1h, Cc, Cc, 0, 0, 0, 0);
    cudaEventRecord(g_sp.eA12, d);
    cudaStreamWaitEvent(d, g_sp.eWall, 0);

    // s1: m2 GEMM (fp16x3, overlapped)
    cudaStreamWaitEvent(s1, g_sp.eA12, 0);
    cudaStreamWaitEvent(s1, g_sp.eWall, 0);
    gemm_sp<0><<<dim3(TDd/128, MTOK/128, 1), 256, GSMEM_SZ, s1>>>(
        a12h + TDd, a12l + TDd, wTh + W2_OFF, wTl + W2_OFF, nullptr, h2h, h2l, m2_b,
        nullptr, nullptr, nullptr, nullptr, 0, MTOK, TDd, TDd, H1h, 0, 0, 0, 0);
    cudaEventRecord(g_sp.eH2, s1);

    // d: m1 -> h1t -> mix -> mT (fp16x3)
    gemm_sp<0><<<dim3(TDd/128, MTOK/128, 1), 256, GSMEM_SZ, d>>>(
        a12h, a12l, wTh + W1_OFF, wTl + W1_OFF, h1, nullptr, nullptr, m1_b,
        nullptr, nullptr, nullptr, nullptr, 0, MTOK, TDd, TDd, H1h, 0, 0, 0, 0);
    transpose_split<<<dim3(TDd/32, Tt/32, Bb), tb, 0, d>>>(h1, h1th, h1tl, Tt, TDd,
        (long long)Tt*TDd, (long long)Tt*TDd);
    cudaStreamWaitEvent(d, g_sp.eXT, 0);
    gemm_sp<1><<<dim3(Cc/128, TDd/128, Bb), 256, GSMEM_SZ, d>>>(
        h1th, h1tl, xTh, xTl, mix, nullptr, nullptr, zb,
        nullptr, nullptr, nullptr, nullptr, 0,
        TDd, Cc, Tt, Tt, (long long)TDd*Tt, (long long)Cc*Tt, (long long)TDd*Cc, 0);
    transpose_split<<<dim3(Cc/32, TDd/32, Bb), tb, 0, d>>>(mix, mTh, mTl, TDd, Cc,
        (long long)TDd*Cc, (long long)TDd*Cc);

    // d: x2 = xln + h2 @ mix (fp16x3; join s1)
    cudaStreamWaitEvent(d, g_sp.eH2, 0);
    gemm_sp<0><<<dim3(Cc/128, Tt/128, Bb), 256, GSMEM_SZ, d>>>(
        h2h, h2l, mTh, mTl, x2, nullptr, nullptr, zb, nullptr, xh, xl, nullptr, 0,
        Tt, Cc, TDd, TDd, (long long)Tt*TDd, (long long)Cc*TDd, (long long)Tt*Cc, (long long)Tt*Cc);

    // d: LN2 (tf32) -> gs (tf32) -> ms (tf32, emit x3 tf32) -> r1 (tf32) -> r2 (tf32)
    ln_tf<<<MTOK, 256, 0, d>>>(x2, ln2_g, ln2_b, xtf);
    gemm_tf<2><<<dim3(CDd/128, MTOK/128, 1), 256, TFSMEM_SZ, d>>>(
        xtf, wgs, nullptr, astf, nullptr, nullptr, bil + 1536, nullptr,
        ssv, CDd/2, MTOK, CDd, Cc, Cc);
    gemm_tf<0><<<dim3(Cc/128, MTOK/128, 1), 256, TFSMEM_SZ, d>>>(
        astf, wms, nullptr, x3tf, nullptr, nullptr, ms_b, x2,
        nullptr, 0, MTOK, Cc, CDd/2, CDd/2);
    gemm_tf<2><<<dim3(Cc/128, MTOK/128, 1), 256, TFSMEM_SZ, d>>>(
        x3tf, wr1, nullptr, artf, nullptr, nullptr, bil + 4608, nullptr,
        nullptr, 0, MTOK, Cc, Cc, Cc);
    gemm_tf<0><<<dim3(Cc/128, MTOK/128, 1), 256, TFSMEM_SZ, d>>>(
        artf, wr2, out, nullptr, nullptr, nullptr, r2_b, nullptr,
        nullptr, 0, MTOK, Cc, Cc/2, Cc/2);
}